// round 1
// baseline (speedup 1.0000x reference)
#include <cuda_runtime.h>
#include <math.h>

#define DIM 512
#define NHEADS 8
#define HD 64
#define BB 2
#define SS 2048
#define MROWS (BB*SS)   // 4096

// Scratch (static device allocation — allowed)
__device__ float g_Q[MROWS * DIM];
__device__ float g_K[MROWS * DIM];
__device__ float g_V[MROWS * DIM];
__device__ float g_A[MROWS * DIM];

// ---------------------------------------------------------------------------
// C[M,N] = A[M,K] @ W[N,K]^T + bias[N]   (NT gemm, all row-major)
// M=4096, N=K=512. 64x64 block tile, 16-deep k tile, 4x4 per thread.
// ---------------------------------------------------------------------------
__global__ __launch_bounds__(256) void gemm_nt(const float* __restrict__ A,
                                               const float* __restrict__ W,
                                               const float* __restrict__ bias,
                                               float* __restrict__ C) {
    const int K = DIM, N = DIM;
    __shared__ float As[16][68];
    __shared__ float Ws[16][68];
    int tid = threadIdx.x;
    int tx = tid & 15, ty = tid >> 4;
    int row0 = blockIdx.y * 64, col0 = blockIdx.x * 64;

    float acc[4][4];
#pragma unroll
    for (int i = 0; i < 4; i++)
#pragma unroll
        for (int j = 0; j < 4; j++) acc[i][j] = 0.f;

    for (int k0 = 0; k0 < K; k0 += 16) {
#pragma unroll
        for (int i = 0; i < 4; i++) {
            int idx = tid + i * 256;
            int r = idx >> 4, c = idx & 15;
            As[c][r] = A[(size_t)(row0 + r) * K + k0 + c];
            Ws[c][r] = W[(size_t)(col0 + r) * K + k0 + c];
        }
        __syncthreads();
#pragma unroll
        for (int kk = 0; kk < 16; kk++) {
            float a[4], b[4];
#pragma unroll
            for (int i = 0; i < 4; i++) a[i] = As[kk][ty * 4 + i];
#pragma unroll
            for (int j = 0; j < 4; j++) b[j] = Ws[kk][tx * 4 + j];
#pragma unroll
            for (int i = 0; i < 4; i++)
#pragma unroll
                for (int j = 0; j < 4; j++) acc[i][j] += a[i] * b[j];
        }
        __syncthreads();
    }
#pragma unroll
    for (int i = 0; i < 4; i++) {
        int r = row0 + ty * 4 + i;
#pragma unroll
        for (int j = 0; j < 4; j++) {
            int cc = col0 + tx * 4 + j;
            C[(size_t)r * N + cc] = acc[i][j] + bias[cc];
        }
    }
}

// ---------------------------------------------------------------------------
// Flash-style attention, fp32. One thread per query row.
// grid = (S/64, H, B), block = 64 threads. K/V tiles of 64 keys in smem.
// Per-thread score scratch in smem with XOR swizzle (conflict-free).
// ---------------------------------------------------------------------------
__global__ __launch_bounds__(64) void attn_kernel(const float* __restrict__ Q,
                                                  const float* __restrict__ Km,
                                                  const float* __restrict__ V,
                                                  float* __restrict__ Out) {
    __shared__ float4 Ks[64 * 16];   // 16 KB
    __shared__ float4 Vs[64 * 16];   // 16 KB
    __shared__ float  ps[64 * 64];   // 16 KB  (total 48 KB exactly)

    const int tid = threadIdx.x;
    const int h = blockIdx.y;
    const int b = blockIdx.z;
    const int q = blockIdx.x * 64 + tid;
    const float scale = 0.125f;  // 1/sqrt(64)

    float4 qv[16];
    const float* qptr = Q + ((size_t)(b * SS + q)) * DIM + h * HD;
#pragma unroll
    for (int i = 0; i < 16; i++) qv[i] = ((const float4*)qptr)[i];

    float m = -1e30f, l = 0.f;
    float4 o[16];
#pragma unroll
    for (int i = 0; i < 16; i++) o[i] = make_float4(0.f, 0.f, 0.f, 0.f);

    for (int kt = 0; kt < SS; kt += 64) {
        const float* kptr = Km + ((size_t)(b * SS + kt + tid)) * DIM + h * HD;
        const float* vptr = V + ((size_t)(b * SS + kt + tid)) * DIM + h * HD;
        __syncthreads();
#pragma unroll
        for (int i = 0; i < 16; i++) {
            Ks[tid * 16 + i] = ((const float4*)kptr)[i];
            Vs[tid * 16 + i] = ((const float4*)vptr)[i];
        }
        __syncthreads();

        // pass 1: scores + running max
        float tmax = m;
#pragma unroll 2
        for (int k = 0; k < 64; k++) {
            float s = 0.f;
#pragma unroll
            for (int i = 0; i < 16; i++) {
                float4 kv = Ks[k * 16 + i];
                s += qv[i].x * kv.x + qv[i].y * kv.y + qv[i].z * kv.z + qv[i].w * kv.w;
            }
            s *= scale;
            ps[tid * 64 + ((k ^ tid) & 63)] = s;
            tmax = fmaxf(tmax, s);
        }

        // rescale accumulators
        float corr = __expf(m - tmax);
        m = tmax;
        l *= corr;
#pragma unroll
        for (int i = 0; i < 16; i++) {
            o[i].x *= corr; o[i].y *= corr; o[i].z *= corr; o[i].w *= corr;
        }

        // pass 2: exp + PV accumulate
#pragma unroll 2
        for (int k = 0; k < 64; k++) {
            float s = ps[tid * 64 + ((k ^ tid) & 63)];
            float pk = __expf(s - m);
            l += pk;
#pragma unroll
            for (int i = 0; i < 16; i++) {
                float4 vv = Vs[k * 16 + i];
                o[i].x += pk * vv.x; o[i].y += pk * vv.y;
                o[i].z += pk * vv.z; o[i].w += pk * vv.w;
            }
        }
    }

    float inv = 1.f / l;
    float* optr = Out + ((size_t)(b * SS + q)) * DIM + h * HD;
#pragma unroll
    for (int i = 0; i < 16; i++) {
        ((float4*)optr)[i] = make_float4(o[i].x * inv, o[i].y * inv,
                                         o[i].z * inv, o[i].w * inv);
    }
}

// ---------------------------------------------------------------------------
// Launch
// Input order (metadata): x, Qexpl, Kexpl, fl, fu, age, gender,
//                         Wq, bq, Wk, bk, Wv, bv, Wo, bo
// ---------------------------------------------------------------------------
extern "C" void kernel_launch(void* const* d_in, const int* in_sizes, int n_in,
                              void* d_out, int out_size) {
    const float* x     = (const float*)d_in[0];
    const float* Qexpl = (const float*)d_in[1];
    const float* Kexpl = (const float*)d_in[2];
    const float* Wq = (const float*)d_in[7];
    const float* bq = (const float*)d_in[8];
    const float* Wk = (const float*)d_in[9];
    const float* bk = (const float*)d_in[10];
    const float* Wv = (const float*)d_in[11];
    const float* bv = (const float*)d_in[12];
    const float* Wo = (const float*)d_in[13];
    const float* bo = (const float*)d_in[14];
    float* out = (float*)d_out;

    float *pQ, *pK, *pV, *pA;
    cudaGetSymbolAddress((void**)&pQ, g_Q);
    cudaGetSymbolAddress((void**)&pK, g_K);
    cudaGetSymbolAddress((void**)&pV, g_V);
    cudaGetSymbolAddress((void**)&pA, g_A);

    dim3 ggrid(DIM / 64, MROWS / 64);
    gemm_nt<<<ggrid, 256>>>(Qexpl, Wq, bq, pQ);
    gemm_nt<<<ggrid, 256>>>(Kexpl, Wk, bk, pK);
    gemm_nt<<<ggrid, 256>>>(x, Wv, bv, pV);

    dim3 agrid(SS / 64, NHEADS, BB);
    attn_kernel<<<agrid, 64>>>(pQ, pK, pV, pA);

    gemm_nt<<<ggrid, 256>>>(pA, Wo, bo, out);
}

// round 2
// speedup vs baseline: 2.2657x; 2.2657x over previous
#include <cuda_runtime.h>
#include <math.h>
#include <stdint.h>

#define DIM 512
#define NHEADS 8
#define HD 64
#define BB 2
#define SS 2048
#define MROWS (BB*SS)   // 4096

// Scratch (static device allocation — allowed)
__device__ float g_Q[MROWS * DIM];
__device__ float g_K[MROWS * DIM];
__device__ float g_V[MROWS * DIM];
__device__ float g_A[MROWS * DIM];

// ---------------------------------------------------------------------------
// helpers
// ---------------------------------------------------------------------------
__device__ __forceinline__ uint32_t f2tf(float x) {
    uint32_t r;
    asm("cvt.rna.tf32.f32 %0, %1;" : "=r"(r) : "f"(x));
    return r;
}

__device__ __forceinline__ void mma_tf32(float c[4],
                                         uint32_t a0, uint32_t a1, uint32_t a2, uint32_t a3,
                                         uint32_t b0, uint32_t b1) {
    asm volatile(
        "mma.sync.aligned.m16n8k8.row.col.f32.tf32.tf32.f32 "
        "{%0,%1,%2,%3}, {%4,%5,%6,%7}, {%8,%9}, {%0,%1,%2,%3};"
        : "+f"(c[0]), "+f"(c[1]), "+f"(c[2]), "+f"(c[3])
        : "r"(a0), "r"(a1), "r"(a2), "r"(a3), "r"(b0), "r"(b1));
}

__device__ __forceinline__ uint4 cvt4(float4 v) {
    return make_uint4(f2tf(v.x), f2tf(v.y), f2tf(v.z), f2tf(v.w));
}

// ---------------------------------------------------------------------------
// C[M,N] = A[M,K] @ W[N,K]^T + bias   (NT, fp32 in/out, tf32 mma)
// M=4096, N=K=512. Block 128 thr (4 warps), 64x64 C tile, 32-deep k chunks.
// smem stride 36 words -> conflict-free fragment loads.
// ---------------------------------------------------------------------------
__global__ __launch_bounds__(128) void gemm_nt_mma(const float* __restrict__ A,
                                                   const float* __restrict__ W,
                                                   const float* __restrict__ bias,
                                                   float* __restrict__ C) {
    __shared__ uint32_t As[64 * 36];
    __shared__ uint32_t Ws[64 * 36];
    const int tid = threadIdx.x;
    const int w = tid >> 5, l = tid & 31;
    const int la = l & 3, lg = l >> 2;
    const int row0 = blockIdx.y * 64, col0 = blockIdx.x * 64;

    float acc[8][4];
#pragma unroll
    for (int j = 0; j < 8; j++)
#pragma unroll
        for (int i = 0; i < 4; i++) acc[j][i] = 0.f;

    for (int kc = 0; kc < DIM; kc += 32) {
        __syncthreads();
#pragma unroll
        for (int i = 0; i < 4; i++) {
            int idx = tid + i * 128;
            int r = idx >> 3, c4 = idx & 7;
            float4 va = *(const float4*)(A + (size_t)(row0 + r) * DIM + kc + c4 * 4);
            *(uint4*)(As + r * 36 + c4 * 4) = cvt4(va);
            float4 vw = *(const float4*)(W + (size_t)(col0 + r) * DIM + kc + c4 * 4);
            *(uint4*)(Ws + r * 36 + c4 * 4) = cvt4(vw);
        }
        __syncthreads();
#pragma unroll
        for (int ks = 0; ks < 4; ks++) {
            uint32_t a0 = As[(16 * w + lg) * 36 + ks * 8 + la];
            uint32_t a1 = As[(16 * w + lg + 8) * 36 + ks * 8 + la];
            uint32_t a2 = As[(16 * w + lg) * 36 + ks * 8 + la + 4];
            uint32_t a3 = As[(16 * w + lg + 8) * 36 + ks * 8 + la + 4];
#pragma unroll
            for (int j = 0; j < 8; j++) {
                uint32_t b0 = Ws[(8 * j + lg) * 36 + ks * 8 + la];
                uint32_t b1 = Ws[(8 * j + lg) * 36 + ks * 8 + la + 4];
                mma_tf32(acc[j], a0, a1, a2, a3, b0, b1);
            }
        }
    }

    const int rA = row0 + 16 * w + lg;
    const int rB = rA + 8;
#pragma unroll
    for (int j = 0; j < 8; j++) {
        int c = col0 + 8 * j + 2 * la;
        float2 bb = *(const float2*)(bias + c);
        *(float2*)(C + (size_t)rA * DIM + c) = make_float2(acc[j][0] + bb.x, acc[j][1] + bb.y);
        *(float2*)(C + (size_t)rB * DIM + c) = make_float2(acc[j][2] + bb.x, acc[j][3] + bb.y);
    }
}

// ---------------------------------------------------------------------------
// Flash attention with tf32 mma. Block = 128 thr (4 warps) = 64 queries,
// key tiles of 64. grid = (S/64, H, B). Dynamic smem: Ks, Vs, Ps (64x68 words).
// ---------------------------------------------------------------------------
#define SMS (64 * 68)

__global__ __launch_bounds__(128) void attn_mma(const float* __restrict__ Q,
                                                const float* __restrict__ Kg,
                                                const float* __restrict__ Vg,
                                                float* __restrict__ Out) {
    extern __shared__ uint32_t sm[];
    uint32_t* Ks = sm;
    uint32_t* Vs = sm + SMS;
    uint32_t* Ps = sm + 2 * SMS;

    const int tid = threadIdx.x;
    const int w = tid >> 5, l = tid & 31;
    const int la = l & 3, lg = l >> 2;
    const int q0 = blockIdx.x * 64;
    const int h = blockIdx.y;
    const int b = blockIdx.z;
    const size_t qbase = (size_t)(b * SS + q0) * DIM + h * HD;
    const int rA = 16 * w + lg;   // local row A; row B = rA + 8

    // Stage Q (pre-scaled by 1/sqrt(hd)=0.125) through Ks, pull frags to regs.
#pragma unroll
    for (int i = 0; i < 8; i++) {
        int idx = tid + i * 128;
        int r = idx >> 4, c4 = idx & 15;
        float4 v = *(const float4*)(Q + qbase + (size_t)r * DIM + c4 * 4);
        *(uint4*)(Ks + r * 68 + c4 * 4) =
            make_uint4(f2tf(v.x * 0.125f), f2tf(v.y * 0.125f),
                       f2tf(v.z * 0.125f), f2tf(v.w * 0.125f));
    }
    __syncthreads();
    uint32_t qf[8][4];
#pragma unroll
    for (int ks = 0; ks < 8; ks++) {
        qf[ks][0] = Ks[rA * 68 + ks * 8 + la];
        qf[ks][1] = Ks[(rA + 8) * 68 + ks * 8 + la];
        qf[ks][2] = Ks[rA * 68 + ks * 8 + la + 4];
        qf[ks][3] = Ks[(rA + 8) * 68 + ks * 8 + la + 4];
    }

    float o[8][4];
#pragma unroll
    for (int j = 0; j < 8; j++)
#pragma unroll
        for (int i = 0; i < 4; i++) o[j][i] = 0.f;
    float mA = -1e30f, mB = -1e30f, lsA = 0.f, lsB = 0.f;

    for (int kt = 0; kt < SS; kt += 64) {
        __syncthreads();  // prior iter done with Ks/Vs
        const size_t kbase = (size_t)(b * SS + kt) * DIM + h * HD;
#pragma unroll
        for (int i = 0; i < 8; i++) {
            int idx = tid + i * 128;
            int r = idx >> 4, c4 = idx & 15;
            float4 kv = *(const float4*)(Kg + kbase + (size_t)r * DIM + c4 * 4);
            *(uint4*)(Ks + r * 68 + c4 * 4) = cvt4(kv);
            float4 vv = *(const float4*)(Vg + kbase + (size_t)r * DIM + c4 * 4);
            *(uint4*)(Vs + r * 68 + c4 * 4) = cvt4(vv);
        }
        __syncthreads();

        // S = Q K^T (scaled)
        float s[8][4];
#pragma unroll
        for (int j = 0; j < 8; j++)
#pragma unroll
            for (int i = 0; i < 4; i++) s[j][i] = 0.f;
#pragma unroll
        for (int ks = 0; ks < 8; ks++) {
#pragma unroll
            for (int j = 0; j < 8; j++) {
                uint32_t b0 = Ks[(8 * j + lg) * 68 + ks * 8 + la];
                uint32_t b1 = Ks[(8 * j + lg) * 68 + ks * 8 + la + 4];
                mma_tf32(s[j], qf[ks][0], qf[ks][1], qf[ks][2], qf[ks][3], b0, b1);
            }
        }

        // online softmax over fragment rows (4-lane quad groups share a row)
        float tA = mA, tB = mB;
#pragma unroll
        for (int j = 0; j < 8; j++) {
            tA = fmaxf(tA, fmaxf(s[j][0], s[j][1]));
            tB = fmaxf(tB, fmaxf(s[j][2], s[j][3]));
        }
        tA = fmaxf(tA, __shfl_xor_sync(0xffffffffu, tA, 1));
        tA = fmaxf(tA, __shfl_xor_sync(0xffffffffu, tA, 2));
        tB = fmaxf(tB, __shfl_xor_sync(0xffffffffu, tB, 1));
        tB = fmaxf(tB, __shfl_xor_sync(0xffffffffu, tB, 2));
        float cA = __expf(mA - tA), cB = __expf(mB - tB);
        mA = tA; mB = tB;
        float sA = 0.f, sB = 0.f;
#pragma unroll
        for (int j = 0; j < 8; j++) {
            float p0 = __expf(s[j][0] - tA);
            float p1 = __expf(s[j][1] - tA);
            float p2 = __expf(s[j][2] - tB);
            float p3 = __expf(s[j][3] - tB);
            sA += p0 + p1; sB += p2 + p3;
            *(uint2*)(Ps + rA * 68 + 8 * j + 2 * la) = make_uint2(f2tf(p0), f2tf(p1));
            *(uint2*)(Ps + (rA + 8) * 68 + 8 * j + 2 * la) = make_uint2(f2tf(p2), f2tf(p3));
        }
        sA += __shfl_xor_sync(0xffffffffu, sA, 1);
        sA += __shfl_xor_sync(0xffffffffu, sA, 2);
        sB += __shfl_xor_sync(0xffffffffu, sB, 1);
        sB += __shfl_xor_sync(0xffffffffu, sB, 2);
        lsA = lsA * cA + sA;
        lsB = lsB * cB + sB;
#pragma unroll
        for (int j = 0; j < 8; j++) {
            o[j][0] *= cA; o[j][1] *= cA; o[j][2] *= cB; o[j][3] *= cB;
        }
        __syncthreads();  // P visible to all warps

        // O += P V
#pragma unroll
        for (int ks = 0; ks < 8; ks++) {
            uint32_t a0 = Ps[rA * 68 + ks * 8 + la];
            uint32_t a1 = Ps[(rA + 8) * 68 + ks * 8 + la];
            uint32_t a2 = Ps[rA * 68 + ks * 8 + la + 4];
            uint32_t a3 = Ps[(rA + 8) * 68 + ks * 8 + la + 4];
#pragma unroll
            for (int j = 0; j < 8; j++) {
                uint32_t b0 = Vs[(ks * 8 + la) * 68 + 8 * j + lg];
                uint32_t b1 = Vs[(ks * 8 + la + 4) * 68 + 8 * j + lg];
                mma_tf32(o[j], a0, a1, a2, a3, b0, b1);
            }
        }
    }

    const float iA = 1.f / lsA, iB = 1.f / lsB;
#pragma unroll
    for (int j = 0; j < 8; j++) {
        int c = 8 * j + 2 * la;
        *(float2*)(Out + qbase + (size_t)rA * DIM + c) =
            make_float2(o[j][0] * iA, o[j][1] * iA);
        *(float2*)(Out + qbase + (size_t)(rA + 8) * DIM + c) =
            make_float2(o[j][2] * iB, o[j][3] * iB);
    }
}

// ---------------------------------------------------------------------------
// Launch. Inputs: x, Qexpl, Kexpl, fl, fu, age, gender,
//                 Wq, bq, Wk, bk, Wv, bv, Wo, bo
// ---------------------------------------------------------------------------
extern "C" void kernel_launch(void* const* d_in, const int* in_sizes, int n_in,
                              void* d_out, int out_size) {
    const float* x     = (const float*)d_in[0];
    const float* Qexpl = (const float*)d_in[1];
    const float* Kexpl = (const float*)d_in[2];
    const float* Wq = (const float*)d_in[7];
    const float* bq = (const float*)d_in[8];
    const float* Wk = (const float*)d_in[9];
    const float* bk = (const float*)d_in[10];
    const float* Wv = (const float*)d_in[11];
    const float* bv = (const float*)d_in[12];
    const float* Wo = (const float*)d_in[13];
    const float* bo = (const float*)d_in[14];
    float* out = (float*)d_out;

    float *pQ, *pK, *pV, *pA;
    cudaGetSymbolAddress((void**)&pQ, g_Q);
    cudaGetSymbolAddress((void**)&pK, g_K);
    cudaGetSymbolAddress((void**)&pV, g_V);
    cudaGetSymbolAddress((void**)&pA, g_A);

    const int attn_smem = 3 * SMS * 4;  // 52224 B
    cudaFuncSetAttribute(attn_mma, cudaFuncAttributeMaxDynamicSharedMemorySize, attn_smem);

    dim3 ggrid(DIM / 64, MROWS / 64);
    gemm_nt_mma<<<ggrid, 128>>>(Qexpl, Wq, bq, pQ);
    gemm_nt_mma<<<ggrid, 128>>>(Kexpl, Wk, bk, pK);
    gemm_nt_mma<<<ggrid, 128>>>(x, Wv, bv, pV);

    dim3 agrid(SS / 64, NHEADS, BB);
    attn_mma<<<agrid, 128, attn_smem>>>(pQ, pK, pV, pA);

    gemm_nt_mma<<<ggrid, 128>>>(pA, Wo, bo, out);
}

// round 3
// speedup vs baseline: 5.9919x; 2.6446x over previous
#include <cuda_runtime.h>
#include <cuda_fp16.h>
#include <math.h>
#include <stdint.h>

#define DIM 512
#define NHEADS 8
#define HD 64
#define BB 2
#define SS 2048
#define MROWS (BB*SS)   // 4096

// Scratch (static device allocation — allowed)
__device__ float g_Q[MROWS * DIM];
__device__ float g_K[MROWS * DIM];
__device__ float g_Vt[DIM * MROWS];   // V projection stored TRANSPOSED: [dim][token]
__device__ float g_A[MROWS * DIM];

// ---------------------------------------------------------------------------
// helpers
// ---------------------------------------------------------------------------
__device__ __forceinline__ void mma_f16(float c[4],
                                        uint32_t a0, uint32_t a1, uint32_t a2, uint32_t a3,
                                        uint32_t b0, uint32_t b1) {
    asm volatile(
        "mma.sync.aligned.m16n8k16.row.col.f32.f16.f16.f32 "
        "{%0,%1,%2,%3}, {%4,%5,%6,%7}, {%8,%9}, {%0,%1,%2,%3};"
        : "+f"(c[0]), "+f"(c[1]), "+f"(c[2]), "+f"(c[3])
        : "r"(a0), "r"(a1), "r"(a2), "r"(a3), "r"(b0), "r"(b1));
}

__device__ __forceinline__ uint32_t h2u(half2 h) { return *(uint32_t*)&h; }

// cvt float4 -> 4 halves packed as uint2
__device__ __forceinline__ uint2 f4h4(float4 v) {
    half2 lo = __floats2half2_rn(v.x, v.y);
    half2 hi = __floats2half2_rn(v.z, v.w);
    return make_uint2(h2u(lo), h2u(hi));
}

#define SSTR 72  // smem row stride in halves (conflict-free for frag loads)

// ---------------------------------------------------------------------------
// C[M,N] = A[M,K] @ W[N,K]^T + bias  (NT, fp32 in/out, fp16 mma m16n8k16)
// Block 128 thr (4 warps), 64x64 tile, 32-deep k chunks.
// If Ct != nullptr, store transposed into Ct[col*MROWS + row] instead of C.
// ---------------------------------------------------------------------------
__device__ __forceinline__ void gemm_body(const float* __restrict__ A,
                                          const float* __restrict__ W,
                                          const float* __restrict__ bias,
                                          float* __restrict__ C,
                                          float* __restrict__ Ct,
                                          int row0, int col0,
                                          half* As, half* Ws) {
    const int tid = threadIdx.x;
    const int w = tid >> 5, lane = tid & 31;
    const int tig = lane & 3, lg = lane >> 2;
    const int rA = 16 * w + lg;

    float acc[8][4];
#pragma unroll
    for (int j = 0; j < 8; j++)
#pragma unroll
        for (int i = 0; i < 4; i++) acc[j][i] = 0.f;

    for (int kc = 0; kc < DIM; kc += 32) {
        __syncthreads();
#pragma unroll
        for (int i = 0; i < 4; i++) {
            int idx = tid + i * 128;            // 512 float4 slots: 64 rows x 8
            int r = idx >> 3, c4 = idx & 7;
            float4 va = *(const float4*)(A + (size_t)(row0 + r) * DIM + kc + c4 * 4);
            *(uint2*)(As + r * SSTR + c4 * 4) = f4h4(va);
            float4 vw = *(const float4*)(W + (size_t)(col0 + r) * DIM + kc + c4 * 4);
            *(uint2*)(Ws + r * SSTR + c4 * 4) = f4h4(vw);
        }
        __syncthreads();
#pragma unroll
        for (int ks = 0; ks < 2; ks++) {
            uint32_t a0 = *(uint32_t*)(As + rA * SSTR + ks * 16 + 2 * tig);
            uint32_t a1 = *(uint32_t*)(As + (rA + 8) * SSTR + ks * 16 + 2 * tig);
            uint32_t a2 = *(uint32_t*)(As + rA * SSTR + ks * 16 + 8 + 2 * tig);
            uint32_t a3 = *(uint32_t*)(As + (rA + 8) * SSTR + ks * 16 + 8 + 2 * tig);
#pragma unroll
            for (int j = 0; j < 8; j++) {
                uint32_t b0 = *(uint32_t*)(Ws + (8 * j + lg) * SSTR + ks * 16 + 2 * tig);
                uint32_t b1 = *(uint32_t*)(Ws + (8 * j + lg) * SSTR + ks * 16 + 8 + 2 * tig);
                mma_f16(acc[j], a0, a1, a2, a3, b0, b1);
            }
        }
    }

    const int gr = row0 + rA;
#pragma unroll
    for (int j = 0; j < 8; j++) {
        int c = col0 + 8 * j + 2 * tig;
        float b0v = bias[c], b1v = bias[c + 1];
        if (Ct) {
            Ct[(size_t)c * MROWS + gr] = acc[j][0] + b0v;
            Ct[(size_t)(c + 1) * MROWS + gr] = acc[j][1] + b1v;
            Ct[(size_t)c * MROWS + gr + 8] = acc[j][2] + b0v;
            Ct[(size_t)(c + 1) * MROWS + gr + 8] = acc[j][3] + b1v;
        } else {
            *(float2*)(C + (size_t)gr * DIM + c) = make_float2(acc[j][0] + b0v, acc[j][1] + b1v);
            *(float2*)(C + (size_t)(gr + 8) * DIM + c) = make_float2(acc[j][2] + b0v, acc[j][3] + b1v);
        }
    }
}

// Fused QKV projections: blockIdx.z selects which projection.
__global__ __launch_bounds__(128) void gemm_qkv(const float* __restrict__ x,
                                                const float* __restrict__ Qe,
                                                const float* __restrict__ Ke,
                                                const float* __restrict__ Wq, const float* __restrict__ bq,
                                                const float* __restrict__ Wk, const float* __restrict__ bk,
                                                const float* __restrict__ Wv, const float* __restrict__ bv,
                                                float* __restrict__ pQ, float* __restrict__ pK,
                                                float* __restrict__ pVt) {
    __shared__ __align__(16) half As[64 * SSTR];
    __shared__ __align__(16) half Ws[64 * SSTR];
    const float *A, *W, *bias;
    float *C = nullptr, *Ct = nullptr;
    if (blockIdx.z == 0)      { A = Qe; W = Wq; bias = bq; C = pQ; }
    else if (blockIdx.z == 1) { A = Ke; W = Wk; bias = bk; C = pK; }
    else                      { A = x;  W = Wv; bias = bv; Ct = pVt; }
    gemm_body(A, W, bias, C, Ct, blockIdx.y * 64, blockIdx.x * 64, As, Ws);
}

__global__ __launch_bounds__(128) void gemm_o(const float* __restrict__ A,
                                              const float* __restrict__ W,
                                              const float* __restrict__ bias,
                                              float* __restrict__ C) {
    __shared__ __align__(16) half As[64 * SSTR];
    __shared__ __align__(16) half Ws[64 * SSTR];
    gemm_body(A, W, bias, C, nullptr, blockIdx.y * 64, blockIdx.x * 64, As, Ws);
}

// ---------------------------------------------------------------------------
// Flash attention, fp16 mma m16n8k16, P kept in registers (FA-2 layout reuse).
// Block = 128 thr (4 warps) = 64 queries; key tiles of 64.
// grid = (S/64, H, B). V read from transposed g_Vt -> smem Vt[hd][key].
// ---------------------------------------------------------------------------
__global__ __launch_bounds__(128) void attn_f16(const float* __restrict__ Qf,
                                                const float* __restrict__ Kf,
                                                const float* __restrict__ Vtf,
                                                float* __restrict__ Out) {
    __shared__ __align__(16) half Ks[64 * SSTR];   // K tile [key][hd]; also Q staging
    __shared__ __align__(16) half Vts[64 * SSTR];  // V^T tile [hd][key]

    const int tid = threadIdx.x;
    const int w = tid >> 5, lane = tid & 31;
    const int tig = lane & 3, lg = lane >> 2;
    const int q0 = blockIdx.x * 64;
    const int h = blockIdx.y;
    const int b = blockIdx.z;
    const size_t qbase = (size_t)(b * SS + q0) * DIM + h * HD;
    const int rA = 16 * w + lg;

    // --- stage Q (pre-scaled by 1/8) into Ks, pull A-fragments to registers
#pragma unroll
    for (int i = 0; i < 8; i++) {
        int idx = tid + i * 128;             // 1024 float4: 64 rows x 16
        int r = idx >> 4, c4 = idx & 15;
        float4 v = *(const float4*)(Qf + qbase + (size_t)r * DIM + c4 * 4);
        v.x *= 0.125f; v.y *= 0.125f; v.z *= 0.125f; v.w *= 0.125f;
        *(uint2*)(Ks + r * SSTR + c4 * 4) = f4h4(v);
    }
    __syncthreads();
    uint32_t qfr[4][4];
#pragma unroll
    for (int ks = 0; ks < 4; ks++) {
        qfr[ks][0] = *(uint32_t*)(Ks + rA * SSTR + ks * 16 + 2 * tig);
        qfr[ks][1] = *(uint32_t*)(Ks + (rA + 8) * SSTR + ks * 16 + 2 * tig);
        qfr[ks][2] = *(uint32_t*)(Ks + rA * SSTR + ks * 16 + 8 + 2 * tig);
        qfr[ks][3] = *(uint32_t*)(Ks + (rA + 8) * SSTR + ks * 16 + 8 + 2 * tig);
    }

    float o[8][4];
#pragma unroll
    for (int j = 0; j < 8; j++)
#pragma unroll
        for (int i = 0; i < 4; i++) o[j][i] = 0.f;
    float mA = -1e30f, mB = -1e30f, lsA = 0.f, lsB = 0.f;

    for (int kt = 0; kt < SS; kt += 64) {
        __syncthreads();
        const size_t kbase = (size_t)(b * SS + kt) * DIM + h * HD;
#pragma unroll
        for (int i = 0; i < 8; i++) {
            int idx = tid + i * 128;
            int r = idx >> 4, c4 = idx & 15;
            float4 kv = *(const float4*)(Kf + kbase + (size_t)r * DIM + c4 * 4);
            *(uint2*)(Ks + r * SSTR + c4 * 4) = f4h4(kv);
        }
#pragma unroll
        for (int i = 0; i < 8; i++) {
            int idx = tid + i * 128;
            int hd = idx >> 4, k4 = (idx & 15) * 4;
            float4 vv = *(const float4*)(Vtf + (size_t)(h * HD + hd) * MROWS + b * SS + kt + k4);
            *(uint2*)(Vts + hd * SSTR + k4) = f4h4(vv);
        }
        __syncthreads();

        // --- S = Q K^T (scaled)
        float s[8][4];
#pragma unroll
        for (int j = 0; j < 8; j++)
#pragma unroll
            for (int i = 0; i < 4; i++) s[j][i] = 0.f;
#pragma unroll
        for (int ks = 0; ks < 4; ks++) {
#pragma unroll
            for (int j = 0; j < 8; j++) {
                uint32_t b0 = *(uint32_t*)(Ks + (8 * j + lg) * SSTR + ks * 16 + 2 * tig);
                uint32_t b1 = *(uint32_t*)(Ks + (8 * j + lg) * SSTR + ks * 16 + 8 + 2 * tig);
                mma_f16(s[j], qfr[ks][0], qfr[ks][1], qfr[ks][2], qfr[ks][3], b0, b1);
            }
        }

        // --- online softmax (rows lg / lg+8; reduce over tig lanes)
        float tA = mA, tB = mB;
#pragma unroll
        for (int j = 0; j < 8; j++) {
            tA = fmaxf(tA, fmaxf(s[j][0], s[j][1]));
            tB = fmaxf(tB, fmaxf(s[j][2], s[j][3]));
        }
        tA = fmaxf(tA, __shfl_xor_sync(0xffffffffu, tA, 1));
        tA = fmaxf(tA, __shfl_xor_sync(0xffffffffu, tA, 2));
        tB = fmaxf(tB, __shfl_xor_sync(0xffffffffu, tB, 1));
        tB = fmaxf(tB, __shfl_xor_sync(0xffffffffu, tB, 2));
        float cA = __expf(mA - tA), cB = __expf(mB - tB);
        mA = tA; mB = tB;
        float sA = 0.f, sB = 0.f;
        uint32_t pa[4][4];
#pragma unroll
        for (int j = 0; j < 8; j++) {
            s[j][0] = __expf(s[j][0] - tA);
            s[j][1] = __expf(s[j][1] - tA);
            s[j][2] = __expf(s[j][2] - tB);
            s[j][3] = __expf(s[j][3] - tB);
            sA += s[j][0] + s[j][1];
            sB += s[j][2] + s[j][3];
        }
#pragma unroll
        for (int kk = 0; kk < 4; kk++) {
            pa[kk][0] = h2u(__floats2half2_rn(s[2 * kk][0], s[2 * kk][1]));
            pa[kk][1] = h2u(__floats2half2_rn(s[2 * kk][2], s[2 * kk][3]));
            pa[kk][2] = h2u(__floats2half2_rn(s[2 * kk + 1][0], s[2 * kk + 1][1]));
            pa[kk][3] = h2u(__floats2half2_rn(s[2 * kk + 1][2], s[2 * kk + 1][3]));
        }
        sA += __shfl_xor_sync(0xffffffffu, sA, 1);
        sA += __shfl_xor_sync(0xffffffffu, sA, 2);
        sB += __shfl_xor_sync(0xffffffffu, sB, 1);
        sB += __shfl_xor_sync(0xffffffffu, sB, 2);
        lsA = lsA * cA + sA;
        lsB = lsB * cB + sB;
#pragma unroll
        for (int j = 0; j < 8; j++) {
            o[j][0] *= cA; o[j][1] *= cA; o[j][2] *= cB; o[j][3] *= cB;
        }

        // --- O += P V  (P from registers, V^T from smem)
#pragma unroll
        for (int kk = 0; kk < 4; kk++) {
#pragma unroll
            for (int j = 0; j < 8; j++) {
                uint32_t b0 = *(uint32_t*)(Vts + (8 * j + lg) * SSTR + kk * 16 + 2 * tig);
                uint32_t b1 = *(uint32_t*)(Vts + (8 * j + lg) * SSTR + kk * 16 + 8 + 2 * tig);
                mma_f16(o[j], pa[kk][0], pa[kk][1], pa[kk][2], pa[kk][3], b0, b1);
            }
        }
    }

    const float iA = 1.f / lsA, iB = 1.f / lsB;
#pragma unroll
    for (int j = 0; j < 8; j++) {
        int c = 8 * j + 2 * tig;
        *(float2*)(Out + qbase + (size_t)rA * DIM + c) =
            make_float2(o[j][0] * iA, o[j][1] * iA);
        *(float2*)(Out + qbase + (size_t)(rA + 8) * DIM + c) =
            make_float2(o[j][2] * iB, o[j][3] * iB);
    }
}

// ---------------------------------------------------------------------------
// Launch. Inputs: x, Qexpl, Kexpl, fl, fu, age, gender,
//                 Wq, bq, Wk, bk, Wv, bv, Wo, bo
// ---------------------------------------------------------------------------
extern "C" void kernel_launch(void* const* d_in, const int* in_sizes, int n_in,
                              void* d_out, int out_size) {
    const float* x     = (const float*)d_in[0];
    const float* Qexpl = (const float*)d_in[1];
    const float* Kexpl = (const float*)d_in[2];
    const float* Wq = (const float*)d_in[7];
    const float* bq = (const float*)d_in[8];
    const float* Wk = (const float*)d_in[9];
    const float* bk = (const float*)d_in[10];
    const float* Wv = (const float*)d_in[11];
    const float* bv = (const float*)d_in[12];
    const float* Wo = (const float*)d_in[13];
    const float* bo = (const float*)d_in[14];
    float* out = (float*)d_out;

    float *pQ, *pK, *pVt, *pA;
    cudaGetSymbolAddress((void**)&pQ, g_Q);
    cudaGetSymbolAddress((void**)&pK, g_K);
    cudaGetSymbolAddress((void**)&pVt, g_Vt);
    cudaGetSymbolAddress((void**)&pA, g_A);

    dim3 qkvgrid(DIM / 64, MROWS / 64, 3);
    gemm_qkv<<<qkvgrid, 128>>>(x, Qexpl, Kexpl, Wq, bq, Wk, bk, Wv, bv, pQ, pK, pVt);

    dim3 agrid(SS / 64, NHEADS, BB);
    attn_f16<<<agrid, 128>>>(pQ, pK, pVt, pA);

    dim3 ogrid(DIM / 64, MROWS / 64);
    gemm_o<<<ogrid, 128>>>(pA, Wo, bo, out);
}

// round 4
// speedup vs baseline: 10.7506x; 1.7942x over previous
#include <cuda_runtime.h>
#include <cuda_fp16.h>
#include <stdint.h>

#define DIM 512
#define NHEADS 8
#define HD 64
#define BB 2
#define SS 2048
#define MROWS (BB*SS)   // 4096

// Scratch (static device allocation — allowed)
__device__ half g_xh[MROWS * DIM];
__device__ half g_qeh[MROWS * DIM];
__device__ half g_keh[MROWS * DIM];
__device__ half g_Wh[4][DIM * DIM];      // Wq, Wk, Wv, Wo as half
__device__ half g_Qh[MROWS * DIM];       // Q proj (pre-scaled by 0.125)
__device__ half g_Kh[MROWS * DIM];
__device__ half g_Vth[DIM * MROWS];      // V proj TRANSPOSED [dim][token]
__device__ half g_Ah[MROWS * DIM];       // attention output (half)

// ---------------------------------------------------------------------------
// helpers
// ---------------------------------------------------------------------------
__device__ __forceinline__ void mma_f16(float c[4],
                                        uint32_t a0, uint32_t a1, uint32_t a2, uint32_t a3,
                                        uint32_t b0, uint32_t b1) {
    asm volatile(
        "mma.sync.aligned.m16n8k16.row.col.f32.f16.f16.f32 "
        "{%0,%1,%2,%3}, {%4,%5,%6,%7}, {%8,%9}, {%0,%1,%2,%3};"
        : "+f"(c[0]), "+f"(c[1]), "+f"(c[2]), "+f"(c[3])
        : "r"(a0), "r"(a1), "r"(a2), "r"(a3), "r"(b0), "r"(b1));
}

__device__ __forceinline__ uint32_t h2u(half2 h) { return *(uint32_t*)&h; }

__device__ __forceinline__ uint2 f4h4(float4 v) {
    half2 lo = __floats2half2_rn(v.x, v.y);
    half2 hi = __floats2half2_rn(v.z, v.w);
    return make_uint2(h2u(lo), h2u(hi));
}

__device__ __forceinline__ void ldm4(uint32_t addr, uint32_t& r0, uint32_t& r1,
                                     uint32_t& r2, uint32_t& r3) {
    asm volatile("ldmatrix.sync.aligned.m8n8.x4.shared.b16 {%0,%1,%2,%3}, [%4];"
                 : "=r"(r0), "=r"(r1), "=r"(r2), "=r"(r3) : "r"(addr));
}

#define CP16(dst, src) \
    asm volatile("cp.async.cg.shared.global [%0], [%1], 16;" :: "r"(dst), "l"(src))
#define CP_COMMIT() asm volatile("cp.async.commit_group;")
#define CP_WAIT1()  asm volatile("cp.async.wait_group 1;")
#define CP_WAIT0()  asm volatile("cp.async.wait_group 0;")

// 64x64-half tile, rows of 128B = 8 chunks of 16B, XOR-swizzled by row&7.
// Byte offset of (row r, 16B-chunk c8):
__device__ __forceinline__ uint32_t swb(int r, int c8) {
    return (uint32_t)(r * 128 + ((c8 ^ (r & 7)) << 4));
}

// ---------------------------------------------------------------------------
// fp32 -> fp16 conversion, 7 planes (x, Qexpl, Kexpl, Wq, Wk, Wv, Wo)
// ---------------------------------------------------------------------------
struct CvtArgs {
    const float* s[7];
    half* d[7];
    int n4[7];   // element count / 4
};

__global__ __launch_bounds__(256) void cvt_all(CvtArgs a) {
    int z = blockIdx.y;
    int n4 = a.n4[z];
    const float4* s = (const float4*)a.s[z];
    half* d = a.d[z];
    for (int i = blockIdx.x * blockDim.x + threadIdx.x; i < n4;
         i += gridDim.x * blockDim.x) {
        float4 v = s[i];
        *(uint2*)(d + (size_t)i * 4) = f4h4(v);
    }
}

// ---------------------------------------------------------------------------
// C[M,N] = A[M,K] @ W[N,K]^T + bias  (NT, half in, fp16 mma, double-buffered
// cp.async, ldmatrix fragment loads). Block 128 thr (4 warps), 64x64 tile.
// Output modes: Cf (fp32 row-major), Ch (half row-major), Ct (half transposed).
// ---------------------------------------------------------------------------
__device__ __forceinline__ void gemm_body(const half* __restrict__ A,
                                          const half* __restrict__ W,
                                          const float* __restrict__ bias,
                                          float scale,
                                          float* Cf, half* Ch, half* Ct,
                                          int row0, int col0, half* smem) {
    const int tid = threadIdx.x;
    const int w = tid >> 5, lane = tid & 31;
    const int tig = lane & 3, lg = lane >> 2;
    const int rA = 16 * w + lg;
    const int m = lane >> 3, l7 = lane & 7;

    uint32_t sbase = (uint32_t)__cvta_generic_to_shared(smem);
    // buffers: [buf][A=0/W=1] each 64*64 halves = 8192 B
    const uint32_t sA[2] = { sbase, sbase + 16384 };
    const uint32_t sW[2] = { sbase + 8192, sbase + 24576 };

    float acc[8][4];
#pragma unroll
    for (int j = 0; j < 8; j++)
#pragma unroll
        for (int i = 0; i < 4; i++) acc[j][i] = 0.f;

    // stage loader: k-chunk kc (64 deep) into buffer bi
    auto load_stage = [&](int bi, int kc) {
#pragma unroll
        for (int i = 0; i < 4; i++) {
            int idx = tid + i * 128;            // 512 chunks per tile
            int r = idx >> 3, c8 = idx & 7;
            CP16(sA[bi] + swb(r, c8), A + (size_t)(row0 + r) * DIM + kc + c8 * 8);
            CP16(sW[bi] + swb(r, c8), W + (size_t)(col0 + r) * DIM + kc + c8 * 8);
        }
        CP_COMMIT();
    };

    load_stage(0, 0);
    for (int c = 0; c < 8; c++) {
        if (c < 7) load_stage((c + 1) & 1, (c + 1) * 64);
        if (c < 7) { CP_WAIT1(); } else { CP_WAIT0(); }
        __syncthreads();
        int bi = c & 1;
#pragma unroll
        for (int ks = 0; ks < 4; ks++) {
            uint32_t a0, a1, a2, a3;
            {
                int rr = 16 * w + ((m & 1) << 3) + l7;
                int c8 = ks * 2 + (m >> 1);
                ldm4(sA[bi] + swb(rr, c8), a0, a1, a2, a3);
            }
#pragma unroll
            for (int jp = 0; jp < 4; jp++) {
                uint32_t b0, b1, b2, b3;
                int rr = (2 * jp + (m >> 1)) * 8 + l7;
                int c8 = ks * 2 + (m & 1);
                ldm4(sW[bi] + swb(rr, c8), b0, b1, b2, b3);
                mma_f16(acc[2 * jp],     a0, a1, a2, a3, b0, b1);
                mma_f16(acc[2 * jp + 1], a0, a1, a2, a3, b2, b3);
            }
        }
        __syncthreads();
    }

    const int gr = row0 + rA;
#pragma unroll
    for (int j = 0; j < 8; j++) {
        int c = col0 + 8 * j + 2 * tig;
        float b0v = bias[c], b1v = bias[c + 1];
        float v0 = (acc[j][0] + b0v) * scale;
        float v1 = (acc[j][1] + b1v) * scale;
        float v2 = (acc[j][2] + b0v) * scale;
        float v3 = (acc[j][3] + b1v) * scale;
        if (Ch) {
            *(half2*)(Ch + (size_t)gr * DIM + c) = __floats2half2_rn(v0, v1);
            *(half2*)(Ch + (size_t)(gr + 8) * DIM + c) = __floats2half2_rn(v2, v3);
        } else if (Ct) {
            Ct[(size_t)c * MROWS + gr] = __float2half(v0);
            Ct[(size_t)(c + 1) * MROWS + gr] = __float2half(v1);
            Ct[(size_t)c * MROWS + gr + 8] = __float2half(v2);
            Ct[(size_t)(c + 1) * MROWS + gr + 8] = __float2half(v3);
        } else {
            *(float2*)(Cf + (size_t)gr * DIM + c) = make_float2(v0, v1);
            *(float2*)(Cf + (size_t)(gr + 8) * DIM + c) = make_float2(v2, v3);
        }
    }
}

__global__ __launch_bounds__(128) void gemm_qkv(const float* __restrict__ bq,
                                                const float* __restrict__ bk,
                                                const float* __restrict__ bv) {
    __shared__ __align__(16) half smem[2 * 2 * 4096];
    int z = blockIdx.z;
    const half* A = (z == 0) ? g_qeh : (z == 1) ? g_keh : g_xh;
    const half* W = g_Wh[z];
    const float* bias = (z == 0) ? bq : (z == 1) ? bk : bv;
    float scale = (z == 0) ? 0.125f : 1.0f;
    half* Ch = (z == 0) ? g_Qh : (z == 1) ? g_Kh : nullptr;
    half* Ct = (z == 2) ? g_Vth : nullptr;
    gemm_body(A, W, bias, scale, nullptr, Ch, Ct,
              blockIdx.y * 64, blockIdx.x * 64, smem);
}

__global__ __launch_bounds__(128) void gemm_o(const float* __restrict__ bo,
                                              float* __restrict__ out) {
    __shared__ __align__(16) half smem[2 * 2 * 4096];
    gemm_body(g_Ah, g_Wh[3], bo, 1.0f, out, nullptr, nullptr,
              blockIdx.y * 64, blockIdx.x * 64, smem);
}

// ---------------------------------------------------------------------------
// Flash attention, fp16 mma, half inputs, cp.async double-buffered K/V tiles,
// ldmatrix fragments, P kept in registers. Block 128 thr = 64 queries.
// grid = (S/64, H, B).
// ---------------------------------------------------------------------------
__global__ __launch_bounds__(128) void attn_f16(float* __restrict__ dummy) {
    __shared__ __align__(16) half smK[2][4096];
    __shared__ __align__(16) half smV[2][4096];

    const int tid = threadIdx.x;
    const int w = tid >> 5, lane = tid & 31;
    const int tig = lane & 3, lg = lane >> 2;
    const int m = lane >> 3, l7 = lane & 7;
    const int q0 = blockIdx.x * 64;
    const int h = blockIdx.y;
    const int b = blockIdx.z;
    const size_t qbase = (size_t)(b * SS + q0) * DIM + h * HD;
    const int rA = 16 * w + lg;

    uint32_t sK[2], sV[2];
    sK[0] = (uint32_t)__cvta_generic_to_shared(smK[0]);
    sK[1] = (uint32_t)__cvta_generic_to_shared(smK[1]);
    sV[0] = (uint32_t)__cvta_generic_to_shared(smV[0]);
    sV[1] = (uint32_t)__cvta_generic_to_shared(smV[1]);

    // ---- stage Q (already pre-scaled in projection) into smK[0]
#pragma unroll
    for (int i = 0; i < 4; i++) {
        int idx = tid + i * 128;
        int r = idx >> 3, c8 = idx & 7;
        CP16(sK[0] + swb(r, c8), g_Qh + qbase + (size_t)r * DIM + c8 * 8);
    }
    CP_COMMIT(); CP_WAIT0();
    __syncthreads();
    uint32_t qfr[4][4];
#pragma unroll
    for (int ks = 0; ks < 4; ks++) {
        int rr = 16 * w + ((m & 1) << 3) + l7;
        int c8 = ks * 2 + (m >> 1);
        ldm4(sK[0] + swb(rr, c8), qfr[ks][0], qfr[ks][1], qfr[ks][2], qfr[ks][3]);
    }
    __syncthreads();

    // stage loader for key-tile t into buffer bi
    auto load_kv = [&](int bi, int kt) {
        const size_t kbase = (size_t)(b * SS + kt) * DIM + h * HD;
#pragma unroll
        for (int i = 0; i < 4; i++) {
            int idx = tid + i * 128;
            int r = idx >> 3, c8 = idx & 7;
            CP16(sK[bi] + swb(r, c8), g_Kh + kbase + (size_t)r * DIM + c8 * 8);
            CP16(sV[bi] + swb(r, c8),
                 g_Vth + (size_t)(h * HD + r) * MROWS + b * SS + kt + c8 * 8);
        }
        CP_COMMIT();
    };

    float o[8][4];
#pragma unroll
    for (int j = 0; j < 8; j++)
#pragma unroll
        for (int i = 0; i < 4; i++) o[j][i] = 0.f;
    float mA = -1e30f, mB = -1e30f, lsA = 0.f, lsB = 0.f;

    load_kv(0, 0);
    for (int t = 0; t < SS / 64; t++) {
        if (t < SS / 64 - 1) load_kv((t + 1) & 1, (t + 1) * 64);
        if (t < SS / 64 - 1) { CP_WAIT1(); } else { CP_WAIT0(); }
        __syncthreads();
        int bi = t & 1;

        // --- S = Q K^T
        float s[8][4];
#pragma unroll
        for (int j = 0; j < 8; j++)
#pragma unroll
            for (int i = 0; i < 4; i++) s[j][i] = 0.f;
#pragma unroll
        for (int ks = 0; ks < 4; ks++) {
#pragma unroll
            for (int jp = 0; jp < 4; jp++) {
                uint32_t b0, b1, b2, b3;
                int rr = (2 * jp + (m >> 1)) * 8 + l7;
                int c8 = ks * 2 + (m & 1);
                ldm4(sK[bi] + swb(rr, c8), b0, b1, b2, b3);
                mma_f16(s[2 * jp],     qfr[ks][0], qfr[ks][1], qfr[ks][2], qfr[ks][3], b0, b1);
                mma_f16(s[2 * jp + 1], qfr[ks][0], qfr[ks][1], qfr[ks][2], qfr[ks][3], b2, b3);
            }
        }

        // --- online softmax
        float tA = mA, tB = mB;
#pragma unroll
        for (int j = 0; j < 8; j++) {
            tA = fmaxf(tA, fmaxf(s[j][0], s[j][1]));
            tB = fmaxf(tB, fmaxf(s[j][2], s[j][3]));
        }
        tA = fmaxf(tA, __shfl_xor_sync(0xffffffffu, tA, 1));
        tA = fmaxf(tA, __shfl_xor_sync(0xffffffffu, tA, 2));
        tB = fmaxf(tB, __shfl_xor_sync(0xffffffffu, tB, 1));
        tB = fmaxf(tB, __shfl_xor_sync(0xffffffffu, tB, 2));
        float cA = __expf(mA - tA), cB = __expf(mB - tB);
        mA = tA; mB = tB;
        float sA = 0.f, sB = 0.f;
#pragma unroll
        for (int j = 0; j < 8; j++) {
            s[j][0] = __expf(s[j][0] - tA);
            s[j][1] = __expf(s[j][1] - tA);
            s[j][2] = __expf(s[j][2] - tB);
            s[j][3] = __expf(s[j][3] - tB);
            sA += s[j][0] + s[j][1];
            sB += s[j][2] + s[j][3];
        }
        uint32_t pa[4][4];
#pragma unroll
        for (int kk = 0; kk < 4; kk++) {
            pa[kk][0] = h2u(__floats2half2_rn(s[2 * kk][0], s[2 * kk][1]));
            pa[kk][1] = h2u(__floats2half2_rn(s[2 * kk][2], s[2 * kk][3]));
            pa[kk][2] = h2u(__floats2half2_rn(s[2 * kk + 1][0], s[2 * kk + 1][1]));
            pa[kk][3] = h2u(__floats2half2_rn(s[2 * kk + 1][2], s[2 * kk + 1][3]));
        }
        sA += __shfl_xor_sync(0xffffffffu, sA, 1);
        sA += __shfl_xor_sync(0xffffffffu, sA, 2);
        sB += __shfl_xor_sync(0xffffffffu, sB, 1);
        sB += __shfl_xor_sync(0xffffffffu, sB, 2);
        lsA = lsA * cA + sA;
        lsB = lsB * cB + sB;
#pragma unroll
        for (int j = 0; j < 8; j++) {
            o[j][0] *= cA; o[j][1] *= cA; o[j][2] *= cB; o[j][3] *= cB;
        }

        // --- O += P V  (P regs, V^T tile rows = hd)
#pragma unroll
        for (int kk = 0; kk < 4; kk++) {
#pragma unroll
            for (int jp = 0; jp < 4; jp++) {
                uint32_t b0, b1, b2, b3;
                int rr = (2 * jp + (m >> 1)) * 8 + l7;
                int c8 = kk * 2 + (m & 1);
                ldm4(sV[bi] + swb(rr, c8), b0, b1, b2, b3);
                mma_f16(o[2 * jp],     pa[kk][0], pa[kk][1], pa[kk][2], pa[kk][3], b0, b1);
                mma_f16(o[2 * jp + 1], pa[kk][0], pa[kk][1], pa[kk][2], pa[kk][3], b2, b3);
            }
        }
        __syncthreads();
    }

    const float iA = 1.f / lsA, iB = 1.f / lsB;
#pragma unroll
    for (int j = 0; j < 8; j++) {
        int c = 8 * j + 2 * tig;
        *(half2*)(g_Ah + qbase + (size_t)rA * DIM + c) =
            __floats2half2_rn(o[j][0] * iA, o[j][1] * iA);
        *(half2*)(g_Ah + qbase + (size_t)(rA + 8) * DIM + c) =
            __floats2half2_rn(o[j][2] * iB, o[j][3] * iB);
    }
}

// ---------------------------------------------------------------------------
// Launch. Inputs: x, Qexpl, Kexpl, fl, fu, age, gender,
//                 Wq, bq, Wk, bk, Wv, bv, Wo, bo
// ---------------------------------------------------------------------------
extern "C" void kernel_launch(void* const* d_in, const int* in_sizes, int n_in,
                              void* d_out, int out_size) {
    const float* x     = (const float*)d_in[0];
    const float* Qexpl = (const float*)d_in[1];
    const float* Kexpl = (const float*)d_in[2];
    const float* Wq = (const float*)d_in[7];
    const float* bq = (const float*)d_in[8];
    const float* Wk = (const float*)d_in[9];
    const float* bk = (const float*)d_in[10];
    const float* Wv = (const float*)d_in[11];
    const float* bv = (const float*)d_in[12];
    const float* Wo = (const float*)d_in[13];
    const float* bo = (const float*)d_in[14];
    float* out = (float*)d_out;

    half *pxh, *pqeh, *pkeh, *pWh;
    cudaGetSymbolAddress((void**)&pxh, g_xh);
    cudaGetSymbolAddress((void**)&pqeh, g_qeh);
    cudaGetSymbolAddress((void**)&pkeh, g_keh);
    cudaGetSymbolAddress((void**)&pWh, g_Wh);

    CvtArgs ca;
    ca.s[0] = x;     ca.d[0] = pxh;                 ca.n4[0] = MROWS * DIM / 4;
    ca.s[1] = Qexpl; ca.d[1] = pqeh;                ca.n4[1] = MROWS * DIM / 4;
    ca.s[2] = Kexpl; ca.d[2] = pkeh;                ca.n4[2] = MROWS * DIM / 4;
    ca.s[3] = Wq;    ca.d[3] = pWh;                 ca.n4[3] = DIM * DIM / 4;
    ca.s[4] = Wk;    ca.d[4] = pWh + DIM * DIM;     ca.n4[4] = DIM * DIM / 4;
    ca.s[5] = Wv;    ca.d[5] = pWh + 2 * DIM * DIM; ca.n4[5] = DIM * DIM / 4;
    ca.s[6] = Wo;    ca.d[6] = pWh + 3 * DIM * DIM; ca.n4[6] = DIM * DIM / 4;
    cvt_all<<<dim3(256, 7), 256>>>(ca);

    dim3 qkvgrid(DIM / 64, MROWS / 64, 3);
    gemm_qkv<<<qkvgrid, 128>>>(bq, bk, bv);

    dim3 agrid(SS / 64, NHEADS, BB);
    attn_f16<<<agrid, 128>>>(nullptr);

    dim3 ogrid(DIM / 64, MROWS / 64);
    gemm_o<<<ogrid, 128>>>(bo, out);
}

// round 5
// speedup vs baseline: 10.8840x; 1.0124x over previous
#include <cuda_runtime.h>
#include <cuda_fp16.h>
#include <stdint.h>

#define DIM 512
#define NHEADS 8
#define HD 64
#define BB 2
#define SS 2048
#define MROWS (BB*SS)   // 4096

// Scratch (static device allocation — allowed)
__device__ half g_xh[MROWS * DIM];
__device__ half g_qeh[MROWS * DIM];
__device__ half g_keh[MROWS * DIM];
__device__ half g_Wh[4][DIM * DIM];      // Wq, Wk, Wv, Wo as half
__device__ half g_Qh[MROWS * DIM];       // Q proj (pre-scaled by 0.125)
__device__ half g_Kh[MROWS * DIM];
__device__ half g_Vth[DIM * MROWS];      // V proj TRANSPOSED [dim][token]
__device__ half g_Ah[MROWS * DIM];       // attention output (half)

// ---------------------------------------------------------------------------
// helpers
// ---------------------------------------------------------------------------
__device__ __forceinline__ void mma_f16(float c[4],
                                        uint32_t a0, uint32_t a1, uint32_t a2, uint32_t a3,
                                        uint32_t b0, uint32_t b1) {
    asm volatile(
        "mma.sync.aligned.m16n8k16.row.col.f32.f16.f16.f32 "
        "{%0,%1,%2,%3}, {%4,%5,%6,%7}, {%8,%9}, {%0,%1,%2,%3};"
        : "+f"(c[0]), "+f"(c[1]), "+f"(c[2]), "+f"(c[3])
        : "r"(a0), "r"(a1), "r"(a2), "r"(a3), "r"(b0), "r"(b1));
}

__device__ __forceinline__ uint32_t h2u(half2 h) { return *(uint32_t*)&h; }

__device__ __forceinline__ uint2 f4h4(float4 v) {
    half2 lo = __floats2half2_rn(v.x, v.y);
    half2 hi = __floats2half2_rn(v.z, v.w);
    return make_uint2(h2u(lo), h2u(hi));
}

__device__ __forceinline__ void ldm4(uint32_t addr, uint32_t& r0, uint32_t& r1,
                                     uint32_t& r2, uint32_t& r3) {
    asm volatile("ldmatrix.sync.aligned.m8n8.x4.shared.b16 {%0,%1,%2,%3}, [%4];"
                 : "=r"(r0), "=r"(r1), "=r"(r2), "=r"(r3) : "r"(addr));
}

#define CP16(dst, src) \
    asm volatile("cp.async.cg.shared.global [%0], [%1], 16;" :: "r"(dst), "l"(src))
#define CP_COMMIT() asm volatile("cp.async.commit_group;")
#define CP_WAIT1()  asm volatile("cp.async.wait_group 1;")
#define CP_WAIT0()  asm volatile("cp.async.wait_group 0;")

// rows of 128B = 8 chunks of 16B, XOR-swizzled by row&7.
__device__ __forceinline__ uint32_t swb(int r, int c8) {
    return (uint32_t)(r * 128 + ((c8 ^ (r & 7)) << 4));
}

// ---------------------------------------------------------------------------
// fp32 -> fp16 conversion, 7 planes
// ---------------------------------------------------------------------------
struct CvtArgs {
    const float* s[7];
    half* d[7];
    int n4[7];
};

__global__ __launch_bounds__(256) void cvt_all(CvtArgs a) {
    int z = blockIdx.y;
    int n4 = a.n4[z];
    const float4* s = (const float4*)a.s[z];
    half* d = a.d[z];
    for (int i = blockIdx.x * blockDim.x + threadIdx.x; i < n4;
         i += gridDim.x * blockDim.x) {
        float4 v = s[i];
        *(uint2*)(d + (size_t)i * 4) = f4h4(v);
    }
}

// ---------------------------------------------------------------------------
// C[M,N] = A[M,K] @ W[N,K]^T + bias  (NT, half in, fp16 mma).
// 128x128 tile, 256 thr (8 warps: 4 row-groups x 2 col-groups, 32x64/warp),
// 64-deep k chunks, double-buffered cp.async, ldmatrix frags.
// ---------------------------------------------------------------------------
__device__ __forceinline__ void gemm_body(const half* __restrict__ A,
                                          const half* __restrict__ W,
                                          const float* __restrict__ bias,
                                          float scale,
                                          float* Cf, half* Ch, half* Ct,
                                          int row0, int col0, half* smem) {
    const int tid = threadIdx.x;
    const int w = tid >> 5, lane = tid & 31;
    const int tig = lane & 3, lg = lane >> 2;
    const int m = lane >> 3, l7 = lane & 7;
    const int wr = w & 3;    // row group (32 rows)
    const int wc = w >> 2;   // col group (64 cols)

    uint32_t sbase = (uint32_t)__cvta_generic_to_shared(smem);
    // stage layout: [buf]{A:16KB, W:16KB}
    const uint32_t sA[2] = { sbase, sbase + 32768 };
    const uint32_t sW[2] = { sbase + 16384, sbase + 49152 };

    float acc[2][8][4];
#pragma unroll
    for (int g = 0; g < 2; g++)
#pragma unroll
        for (int j = 0; j < 8; j++)
#pragma unroll
            for (int i = 0; i < 4; i++) acc[g][j][i] = 0.f;

    auto load_stage = [&](int bi, int kc) {
#pragma unroll
        for (int i = 0; i < 4; i++) {
            int idx = tid + i * 256;            // 1024 chunks per operand
            int r = idx >> 3, c8 = idx & 7;
            CP16(sA[bi] + swb(r, c8), A + (size_t)(row0 + r) * DIM + kc + c8 * 8);
            CP16(sW[bi] + swb(r, c8), W + (size_t)(col0 + r) * DIM + kc + c8 * 8);
        }
        CP_COMMIT();
    };

    load_stage(0, 0);
    for (int c = 0; c < 8; c++) {
        if (c < 7) load_stage((c + 1) & 1, (c + 1) * 64);
        if (c < 7) { CP_WAIT1(); } else { CP_WAIT0(); }
        __syncthreads();
        int bi = c & 1;
#pragma unroll
        for (int ks = 0; ks < 4; ks++) {
            uint32_t af[2][4];
#pragma unroll
            for (int g = 0; g < 2; g++) {
                int rr = wr * 32 + g * 16 + ((m & 1) << 3) + l7;
                int c8 = ks * 2 + (m >> 1);
                ldm4(sA[bi] + swb(rr, c8), af[g][0], af[g][1], af[g][2], af[g][3]);
            }
#pragma unroll
            for (int jp = 0; jp < 4; jp++) {
                uint32_t b0, b1, b2, b3;
                int rr = wc * 64 + (2 * jp + (m >> 1)) * 8 + l7;
                int c8 = ks * 2 + (m & 1);
                ldm4(sW[bi] + swb(rr, c8), b0, b1, b2, b3);
#pragma unroll
                for (int g = 0; g < 2; g++) {
                    mma_f16(acc[g][2 * jp],     af[g][0], af[g][1], af[g][2], af[g][3], b0, b1);
                    mma_f16(acc[g][2 * jp + 1], af[g][0], af[g][1], af[g][2], af[g][3], b2, b3);
                }
            }
        }
        __syncthreads();
    }

#pragma unroll
    for (int g = 0; g < 2; g++) {
        const int gr = row0 + wr * 32 + g * 16 + lg;
#pragma unroll
        for (int j = 0; j < 8; j++) {
            int c = col0 + wc * 64 + 8 * j + 2 * tig;
            float b0v = bias[c], b1v = bias[c + 1];
            float v0 = (acc[g][j][0] + b0v) * scale;
            float v1 = (acc[g][j][1] + b1v) * scale;
            float v2 = (acc[g][j][2] + b0v) * scale;
            float v3 = (acc[g][j][3] + b1v) * scale;
            if (Ch) {
                *(half2*)(Ch + (size_t)gr * DIM + c) = __floats2half2_rn(v0, v1);
                *(half2*)(Ch + (size_t)(gr + 8) * DIM + c) = __floats2half2_rn(v2, v3);
            } else if (Ct) {
                Ct[(size_t)c * MROWS + gr] = __float2half(v0);
                Ct[(size_t)(c + 1) * MROWS + gr] = __float2half(v1);
                Ct[(size_t)c * MROWS + gr + 8] = __float2half(v2);
                Ct[(size_t)(c + 1) * MROWS + gr + 8] = __float2half(v3);
            } else {
                *(float2*)(Cf + (size_t)gr * DIM + c) = make_float2(v0, v1);
                *(float2*)(Cf + (size_t)(gr + 8) * DIM + c) = make_float2(v2, v3);
            }
        }
    }
}

#define GEMM_SMEM 65536

__global__ __launch_bounds__(256) void gemm_qkv(const float* __restrict__ bq,
                                                const float* __restrict__ bk,
                                                const float* __restrict__ bv) {
    extern __shared__ __align__(16) half smem[];
    int z = blockIdx.z;
    const half* A = (z == 0) ? g_qeh : (z == 1) ? g_keh : g_xh;
    const half* W = g_Wh[z];
    const float* bias = (z == 0) ? bq : (z == 1) ? bk : bv;
    float scale = (z == 0) ? 0.125f : 1.0f;
    half* Ch = (z == 0) ? g_Qh : (z == 1) ? g_Kh : nullptr;
    half* Ct = (z == 2) ? g_Vth : nullptr;
    gemm_body(A, W, bias, scale, nullptr, Ch, Ct,
              blockIdx.y * 128, blockIdx.x * 128, smem);
}

__global__ __launch_bounds__(256) void gemm_o(const float* __restrict__ bo,
                                              float* __restrict__ out) {
    extern __shared__ __align__(16) half smem[];
    gemm_body(g_Ah, g_Wh[3], bo, 1.0f, out, nullptr, nullptr,
              blockIdx.y * 128, blockIdx.x * 128, smem);
}

// ---------------------------------------------------------------------------
// Flash attention: 128 queries/block, 256 thr (8 warps x 16 rows), fp16 mma,
// cp.async double-buffered 64-key K/V tiles, P in registers.
// grid = (S/128, H, B).
// ---------------------------------------------------------------------------
__global__ __launch_bounds__(256) void attn_f16(float* __restrict__ dummy) {
    __shared__ __align__(16) half smK[2][4096];
    __shared__ __align__(16) half smV[2][4096];

    const int tid = threadIdx.x;
    const int w = tid >> 5, lane = tid & 31;
    const int tig = lane & 3, lg = lane >> 2;
    const int m = lane >> 3, l7 = lane & 7;
    const int q0 = blockIdx.x * 128;
    const int h = blockIdx.y;
    const int b = blockIdx.z;
    const size_t qbase = (size_t)(b * SS + q0) * DIM + h * HD;
    const int rA = 16 * w + lg;

    uint32_t sK[2], sV[2];
    sK[0] = (uint32_t)__cvta_generic_to_shared(smK[0]);
    sK[1] = (uint32_t)__cvta_generic_to_shared(smK[1]);
    sV[0] = (uint32_t)__cvta_generic_to_shared(smV[0]);
    sV[1] = (uint32_t)__cvta_generic_to_shared(smV[1]);

    // ---- stage Q (128 rows x 64) through smK[0..1] (16KB contiguous)
#pragma unroll
    for (int i = 0; i < 4; i++) {
        int idx = tid + i * 256;                 // 1024 chunks
        int r = idx >> 3, c8 = idx & 7;
        CP16(sK[0] + swb(r, c8), g_Qh + qbase + (size_t)r * DIM + c8 * 8);
    }
    CP_COMMIT(); CP_WAIT0();
    __syncthreads();
    uint32_t qfr[4][4];
#pragma unroll
    for (int ks = 0; ks < 4; ks++) {
        int rr = 16 * w + ((m & 1) << 3) + l7;   // 0..127 spans both buffers
        int c8 = ks * 2 + (m >> 1);
        ldm4(sK[0] + swb(rr, c8), qfr[ks][0], qfr[ks][1], qfr[ks][2], qfr[ks][3]);
    }
    __syncthreads();

    auto load_kv = [&](int bi, int kt) {
        const size_t kbase = (size_t)(b * SS + kt) * DIM + h * HD;
#pragma unroll
        for (int i = 0; i < 2; i++) {
            int idx = tid + i * 256;             // 512 chunks per plane
            int r = idx >> 3, c8 = idx & 7;
            CP16(sK[bi] + swb(r, c8), g_Kh + kbase + (size_t)r * DIM + c8 * 8);
            CP16(sV[bi] + swb(r, c8),
                 g_Vth + (size_t)(h * HD + r) * MROWS + b * SS + kt + c8 * 8);
        }
        CP_COMMIT();
    };

    float o[8][4];
#pragma unroll
    for (int j = 0; j < 8; j++)
#pragma unroll
        for (int i = 0; i < 4; i++) o[j][i] = 0.f;
    float mA = -1e30f, mB = -1e30f, lsA = 0.f, lsB = 0.f;

    load_kv(0, 0);
    for (int t = 0; t < SS / 64; t++) {
        if (t < SS / 64 - 1) load_kv((t + 1) & 1, (t + 1) * 64);
        if (t < SS / 64 - 1) { CP_WAIT1(); } else { CP_WAIT0(); }
        __syncthreads();
        int bi = t & 1;

        // --- S = Q K^T
        float s[8][4];
#pragma unroll
        for (int j = 0; j < 8; j++)
#pragma unroll
            for (int i = 0; i < 4; i++) s[j][i] = 0.f;
#pragma unroll
        for (int ks = 0; ks < 4; ks++) {
#pragma unroll
            for (int jp = 0; jp < 4; jp++) {
                uint32_t b0, b1, b2, b3;
                int rr = (2 * jp + (m >> 1)) * 8 + l7;
                int c8 = ks * 2 + (m & 1);
                ldm4(sK[bi] + swb(rr, c8), b0, b1, b2, b3);
                mma_f16(s[2 * jp],     qfr[ks][0], qfr[ks][1], qfr[ks][2], qfr[ks][3], b0, b1);
                mma_f16(s[2 * jp + 1], qfr[ks][0], qfr[ks][1], qfr[ks][2], qfr[ks][3], b2, b3);
            }
        }

        // --- online softmax
        float tA = mA, tB = mB;
#pragma unroll
        for (int j = 0; j < 8; j++) {
            tA = fmaxf(tA, fmaxf(s[j][0], s[j][1]));
            tB = fmaxf(tB, fmaxf(s[j][2], s[j][3]));
        }
        tA = fmaxf(tA, __shfl_xor_sync(0xffffffffu, tA, 1));
        tA = fmaxf(tA, __shfl_xor_sync(0xffffffffu, tA, 2));
        tB = fmaxf(tB, __shfl_xor_sync(0xffffffffu, tB, 1));
        tB = fmaxf(tB, __shfl_xor_sync(0xffffffffu, tB, 2));
        float cA = __expf(mA - tA), cB = __expf(mB - tB);
        mA = tA; mB = tB;
        float sA = 0.f, sB = 0.f;
#pragma unroll
        for (int j = 0; j < 8; j++) {
            s[j][0] = __expf(s[j][0] - tA);
            s[j][1] = __expf(s[j][1] - tA);
            s[j][2] = __expf(s[j][2] - tB);
            s[j][3] = __expf(s[j][3] - tB);
            sA += s[j][0] + s[j][1];
            sB += s[j][2] + s[j][3];
        }
        uint32_t pa[4][4];
#pragma unroll
        for (int kk = 0; kk < 4; kk++) {
            pa[kk][0] = h2u(__floats2half2_rn(s[2 * kk][0], s[2 * kk][1]));
            pa[kk][1] = h2u(__floats2half2_rn(s[2 * kk][2], s[2 * kk][3]));
            pa[kk][2] = h2u(__floats2half2_rn(s[2 * kk + 1][0], s[2 * kk + 1][1]));
            pa[kk][3] = h2u(__floats2half2_rn(s[2 * kk + 1][2], s[2 * kk + 1][3]));
        }
        sA += __shfl_xor_sync(0xffffffffu, sA, 1);
        sA += __shfl_xor_sync(0xffffffffu, sA, 2);
        sB += __shfl_xor_sync(0xffffffffu, sB, 1);
        sB += __shfl_xor_sync(0xffffffffu, sB, 2);
        lsA = lsA * cA + sA;
        lsB = lsB * cB + sB;
#pragma unroll
        for (int j = 0; j < 8; j++) {
            o[j][0] *= cA; o[j][1] *= cA; o[j][2] *= cB; o[j][3] *= cB;
        }

        // --- O += P V
#pragma unroll
        for (int kk = 0; kk < 4; kk++) {
#pragma unroll
            for (int jp = 0; jp < 4; jp++) {
                uint32_t b0, b1, b2, b3;
                int rr = (2 * jp + (m >> 1)) * 8 + l7;
                int c8 = kk * 2 + (m & 1);
                ldm4(sV[bi] + swb(rr, c8), b0, b1, b2, b3);
                mma_f16(o[2 * jp],     pa[kk][0], pa[kk][1], pa[kk][2], pa[kk][3], b0, b1);
                mma_f16(o[2 * jp + 1], pa[kk][0], pa[kk][1], pa[kk][2], pa[kk][3], b2, b3);
            }
        }
        __syncthreads();
    }

    const float iA = 1.f / lsA, iB = 1.f / lsB;
#pragma unroll
    for (int j = 0; j < 8; j++) {
        int c = 8 * j + 2 * tig;
        *(half2*)(g_Ah + qbase + (size_t)rA * DIM + c) =
            __floats2half2_rn(o[j][0] * iA, o[j][1] * iA);
        *(half2*)(g_Ah + qbase + (size_t)(rA + 8) * DIM + c) =
            __floats2half2_rn(o[j][2] * iB, o[j][3] * iB);
    }
}

// ---------------------------------------------------------------------------
// Launch. Inputs: x, Qexpl, Kexpl, fl, fu, age, gender,
//                 Wq, bq, Wk, bk, Wv, bv, Wo, bo
// ---------------------------------------------------------------------------
extern "C" void kernel_launch(void* const* d_in, const int* in_sizes, int n_in,
                              void* d_out, int out_size) {
    const float* x     = (const float*)d_in[0];
    const float* Qexpl = (const float*)d_in[1];
    const float* Kexpl = (const float*)d_in[2];
    const float* Wq = (const float*)d_in[7];
    const float* bq = (const float*)d_in[8];
    const float* Wk = (const float*)d_in[9];
    const float* bk = (const float*)d_in[10];
    const float* Wv = (const float*)d_in[11];
    const float* bv = (const float*)d_in[12];
    const float* Wo = (const float*)d_in[13];
    const float* bo = (const float*)d_in[14];
    float* out = (float*)d_out;

    half *pxh, *pqeh, *pkeh, *pWh;
    cudaGetSymbolAddress((void**)&pxh, g_xh);
    cudaGetSymbolAddress((void**)&pqeh, g_qeh);
    cudaGetSymbolAddress((void**)&pkeh, g_keh);
    cudaGetSymbolAddress((void**)&pWh, g_Wh);

    static int smem_set = 0;
    if (!smem_set) {
        cudaFuncSetAttribute(gemm_qkv, cudaFuncAttributeMaxDynamicSharedMemorySize, GEMM_SMEM);
        cudaFuncSetAttribute(gemm_o, cudaFuncAttributeMaxDynamicSharedMemorySize, GEMM_SMEM);
        smem_set = 1;
    }

    CvtArgs ca;
    ca.s[0] = x;     ca.d[0] = pxh;                 ca.n4[0] = MROWS * DIM / 4;
    ca.s[1] = Qexpl; ca.d[1] = pqeh;                ca.n4[1] = MROWS * DIM / 4;
    ca.s[2] = Kexpl; ca.d[2] = pkeh;                ca.n4[2] = MROWS * DIM / 4;
    ca.s[3] = Wq;    ca.d[3] = pWh;                 ca.n4[3] = DIM * DIM / 4;
    ca.s[4] = Wk;    ca.d[4] = pWh + DIM * DIM;     ca.n4[4] = DIM * DIM / 4;
    ca.s[5] = Wv;    ca.d[5] = pWh + 2 * DIM * DIM; ca.n4[5] = DIM * DIM / 4;
    ca.s[6] = Wo;    ca.d[6] = pWh + 3 * DIM * DIM; ca.n4[6] = DIM * DIM / 4;
    cvt_all<<<dim3(256, 7), 256>>>(ca);

    dim3 qkvgrid(DIM / 128, MROWS / 128, 3);
    gemm_qkv<<<qkvgrid, 256, GEMM_SMEM>>>(bq, bk, bv);

    dim3 agrid(SS / 128, NHEADS, BB);
    attn_f16<<<agrid, 256>>>(nullptr);

    dim3 ogrid(DIM / 128, MROWS / 128);
    gemm_o<<<ogrid, 256, GEMM_SMEM>>>(bo, out);
}

// round 6
// speedup vs baseline: 11.5014x; 1.0567x over previous
#include <cuda_runtime.h>
#include <cuda_fp16.h>
#include <stdint.h>

#define DIM 512
#define NHEADS 8
#define HD 64
#define BB 2
#define SS 2048
#define MROWS (BB*SS)   // 4096

// Scratch (static device allocation — allowed)
__device__ half g_xh[MROWS * DIM];
__device__ half g_qeh[MROWS * DIM];
__device__ half g_keh[MROWS * DIM];
__device__ half g_Wh[4][DIM * DIM];      // Wq, Wk, Wv, Wo as half
__device__ half g_Qh[MROWS * DIM];       // Q proj (pre-scaled by 0.125)
__device__ half g_Kh[MROWS * DIM];
__device__ half g_Vth[DIM * MROWS];      // V proj TRANSPOSED [dim][token]
__device__ half g_Ah[MROWS * DIM];       // attention output (half)

// ---------------------------------------------------------------------------
// helpers
// ---------------------------------------------------------------------------
__device__ __forceinline__ void mma_f16(float c[4],
                                        uint32_t a0, uint32_t a1, uint32_t a2, uint32_t a3,
                                        uint32_t b0, uint32_t b1) {
    asm volatile(
        "mma.sync.aligned.m16n8k16.row.col.f32.f16.f16.f32 "
        "{%0,%1,%2,%3}, {%4,%5,%6,%7}, {%8,%9}, {%0,%1,%2,%3};"
        : "+f"(c[0]), "+f"(c[1]), "+f"(c[2]), "+f"(c[3])
        : "r"(a0), "r"(a1), "r"(a2), "r"(a3), "r"(b0), "r"(b1));
}

__device__ __forceinline__ uint32_t h2u(half2 h) { return *(uint32_t*)&h; }

__device__ __forceinline__ uint2 f4h4(float4 v) {
    half2 lo = __floats2half2_rn(v.x, v.y);
    half2 hi = __floats2half2_rn(v.z, v.w);
    return make_uint2(h2u(lo), h2u(hi));
}

__device__ __forceinline__ void ldm4(uint32_t addr, uint32_t& r0, uint32_t& r1,
                                     uint32_t& r2, uint32_t& r3) {
    asm volatile("ldmatrix.sync.aligned.m8n8.x4.shared.b16 {%0,%1,%2,%3}, [%4];"
                 : "=r"(r0), "=r"(r1), "=r"(r2), "=r"(r3) : "r"(addr));
}

#define CP16(dst, src) \
    asm volatile("cp.async.cg.shared.global [%0], [%1], 16;" :: "r"(dst), "l"(src))
#define CP_COMMIT() asm volatile("cp.async.commit_group;")
#define CP_WAIT1()  asm volatile("cp.async.wait_group 1;")
#define CP_WAIT0()  asm volatile("cp.async.wait_group 0;")

// rows of 128B = 8 chunks of 16B, XOR-swizzled by row&7.
__device__ __forceinline__ uint32_t swb(int r, int c8) {
    return (uint32_t)(r * 128 + ((c8 ^ (r & 7)) << 4));
}

// ---------------------------------------------------------------------------
// fp32 -> fp16 conversion, 7 planes
// ---------------------------------------------------------------------------
struct CvtArgs {
    const float* s[7];
    half* d[7];
    int n4[7];
};

__global__ __launch_bounds__(256) void cvt_all(CvtArgs a) {
    int z = blockIdx.y;
    int n4 = a.n4[z];
    const float4* s = (const float4*)a.s[z];
    half* d = a.d[z];
    for (int i = blockIdx.x * blockDim.x + threadIdx.x; i < n4;
         i += gridDim.x * blockDim.x) {
        float4 v = s[i];
        *(uint2*)(d + (size_t)i * 4) = f4h4(v);
    }
}

// ---------------------------------------------------------------------------
// C[M,N] = A[M,K] @ W[N,K]^T + bias  (NT, half in, fp16 mma).
// 128x128 tile, 256 thr (8 warps: 4 row-groups x 2 col-groups, 32x64/warp),
// 64-deep k chunks, double-buffered cp.async, ldmatrix frags.
// ---------------------------------------------------------------------------
__device__ __forceinline__ void gemm_body(const half* __restrict__ A,
                                          const half* __restrict__ W,
                                          const float* __restrict__ bias,
                                          float scale,
                                          float* Cf, half* Ch, half* Ct,
                                          int row0, int col0, half* smem) {
    const int tid = threadIdx.x;
    const int w = tid >> 5, lane = tid & 31;
    const int tig = lane & 3, lg = lane >> 2;
    const int m = lane >> 3, l7 = lane & 7;
    const int wr = w & 3;    // row group (32 rows)
    const int wc = w >> 2;   // col group (64 cols)

    uint32_t sbase = (uint32_t)__cvta_generic_to_shared(smem);
    const uint32_t sA[2] = { sbase, sbase + 32768 };
    const uint32_t sW[2] = { sbase + 16384, sbase + 49152 };

    float acc[2][8][4];
#pragma unroll
    for (int g = 0; g < 2; g++)
#pragma unroll
        for (int j = 0; j < 8; j++)
#pragma unroll
            for (int i = 0; i < 4; i++) acc[g][j][i] = 0.f;

    auto load_stage = [&](int bi, int kc) {
#pragma unroll
        for (int i = 0; i < 4; i++) {
            int idx = tid + i * 256;
            int r = idx >> 3, c8 = idx & 7;
            CP16(sA[bi] + swb(r, c8), A + (size_t)(row0 + r) * DIM + kc + c8 * 8);
            CP16(sW[bi] + swb(r, c8), W + (size_t)(col0 + r) * DIM + kc + c8 * 8);
        }
        CP_COMMIT();
    };

    load_stage(0, 0);
    for (int c = 0; c < 8; c++) {
        if (c < 7) load_stage((c + 1) & 1, (c + 1) * 64);
        if (c < 7) { CP_WAIT1(); } else { CP_WAIT0(); }
        __syncthreads();
        int bi = c & 1;
#pragma unroll
        for (int ks = 0; ks < 4; ks++) {
            uint32_t af[2][4];
#pragma unroll
            for (int g = 0; g < 2; g++) {
                int rr = wr * 32 + g * 16 + ((m & 1) << 3) + l7;
                int c8 = ks * 2 + (m >> 1);
                ldm4(sA[bi] + swb(rr, c8), af[g][0], af[g][1], af[g][2], af[g][3]);
            }
#pragma unroll
            for (int jp = 0; jp < 4; jp++) {
                uint32_t b0, b1, b2, b3;
                int rr = wc * 64 + (2 * jp + (m >> 1)) * 8 + l7;
                int c8 = ks * 2 + (m & 1);
                ldm4(sW[bi] + swb(rr, c8), b0, b1, b2, b3);
#pragma unroll
                for (int g = 0; g < 2; g++) {
                    mma_f16(acc[g][2 * jp],     af[g][0], af[g][1], af[g][2], af[g][3], b0, b1);
                    mma_f16(acc[g][2 * jp + 1], af[g][0], af[g][1], af[g][2], af[g][3], b2, b3);
                }
            }
        }
        __syncthreads();
    }

#pragma unroll
    for (int g = 0; g < 2; g++) {
        const int gr = row0 + wr * 32 + g * 16 + lg;
#pragma unroll
        for (int j = 0; j < 8; j++) {
            int c = col0 + wc * 64 + 8 * j + 2 * tig;
            float b0v = bias[c], b1v = bias[c + 1];
            float v0 = (acc[g][j][0] + b0v) * scale;
            float v1 = (acc[g][j][1] + b1v) * scale;
            float v2 = (acc[g][j][2] + b0v) * scale;
            float v3 = (acc[g][j][3] + b1v) * scale;
            if (Ch) {
                *(half2*)(Ch + (size_t)gr * DIM + c) = __floats2half2_rn(v0, v1);
                *(half2*)(Ch + (size_t)(gr + 8) * DIM + c) = __floats2half2_rn(v2, v3);
            } else if (Ct) {
                Ct[(size_t)c * MROWS + gr] = __float2half(v0);
                Ct[(size_t)(c + 1) * MROWS + gr] = __float2half(v1);
                Ct[(size_t)c * MROWS + gr + 8] = __float2half(v2);
                Ct[(size_t)(c + 1) * MROWS + gr + 8] = __float2half(v3);
            } else {
                *(float2*)(Cf + (size_t)gr * DIM + c) = make_float2(v0, v1);
                *(float2*)(Cf + (size_t)(gr + 8) * DIM + c) = make_float2(v2, v3);
            }
        }
    }
}

#define GEMM_SMEM 65536

__global__ __launch_bounds__(256, 2) void gemm_qkv(const float* __restrict__ bq,
                                                   const float* __restrict__ bk,
                                                   const float* __restrict__ bv) {
    extern __shared__ __align__(16) half smem[];
    int z = blockIdx.z;
    const half* A = (z == 0) ? g_qeh : (z == 1) ? g_keh : g_xh;
    const half* W = g_Wh[z];
    const float* bias = (z == 0) ? bq : (z == 1) ? bk : bv;
    float scale = (z == 0) ? 0.125f : 1.0f;
    half* Ch = (z == 0) ? g_Qh : (z == 1) ? g_Kh : nullptr;
    half* Ct = (z == 2) ? g_Vth : nullptr;
    gemm_body(A, W, bias, scale, nullptr, Ch, Ct,
              blockIdx.y * 128, blockIdx.x * 128, smem);
}

__global__ __launch_bounds__(256, 2) void gemm_o(const float* __restrict__ bo,
                                                 float* __restrict__ out) {
    extern __shared__ __align__(16) half smem[];
    gemm_body(g_Ah, g_Wh[3], bo, 1.0f, out, nullptr, nullptr,
              blockIdx.y * 128, blockIdx.x * 128, smem);
}

// ---------------------------------------------------------------------------
// Flash attention: 128 queries/block, 256 thr (8 warps x 16 rows), fp16 mma.
// 64-key smem tiles (double-buffered cp.async), processed as TWO 32-key
// softmax chunks to cut live registers (s[4][4], pa[2][4]) so 2 CTAs/SM fit.
// grid = (S/128, H, B).
// ---------------------------------------------------------------------------
__global__ __launch_bounds__(256, 2) void attn_f16(float* __restrict__ dummy) {
    __shared__ __align__(16) half smK[2][4096];
    __shared__ __align__(16) half smV[2][4096];

    const int tid = threadIdx.x;
    const int w = tid >> 5, lane = tid & 31;
    const int tig = lane & 3, lg = lane >> 2;
    const int m = lane >> 3, l7 = lane & 7;
    const int q0 = blockIdx.x * 128;
    const int h = blockIdx.y;
    const int b = blockIdx.z;
    const size_t qbase = (size_t)(b * SS + q0) * DIM + h * HD;
    const int rA = 16 * w + lg;

    uint32_t sK[2], sV[2];
    sK[0] = (uint32_t)__cvta_generic_to_shared(smK[0]);
    sK[1] = (uint32_t)__cvta_generic_to_shared(smK[1]);
    sV[0] = (uint32_t)__cvta_generic_to_shared(smV[0]);
    sV[1] = (uint32_t)__cvta_generic_to_shared(smV[1]);

    // ---- stage Q (128 rows x 64) through smK[0..1] (16KB contiguous)
#pragma unroll
    for (int i = 0; i < 4; i++) {
        int idx = tid + i * 256;
        int r = idx >> 3, c8 = idx & 7;
        CP16(sK[0] + swb(r, c8), g_Qh + qbase + (size_t)r * DIM + c8 * 8);
    }
    CP_COMMIT(); CP_WAIT0();
    __syncthreads();
    uint32_t qfr[4][4];
#pragma unroll
    for (int ks = 0; ks < 4; ks++) {
        int rr = 16 * w + ((m & 1) << 3) + l7;
        int c8 = ks * 2 + (m >> 1);
        ldm4(sK[0] + swb(rr, c8), qfr[ks][0], qfr[ks][1], qfr[ks][2], qfr[ks][3]);
    }
    __syncthreads();

    auto load_kv = [&](int bi, int kt) {
        const size_t kbase = (size_t)(b * SS + kt) * DIM + h * HD;
#pragma unroll
        for (int i = 0; i < 2; i++) {
            int idx = tid + i * 256;
            int r = idx >> 3, c8 = idx & 7;
            CP16(sK[bi] + swb(r, c8), g_Kh + kbase + (size_t)r * DIM + c8 * 8);
            CP16(sV[bi] + swb(r, c8),
                 g_Vth + (size_t)(h * HD + r) * MROWS + b * SS + kt + c8 * 8);
        }
        CP_COMMIT();
    };

    float o[8][4];
#pragma unroll
    for (int j = 0; j < 8; j++)
#pragma unroll
        for (int i = 0; i < 4; i++) o[j][i] = 0.f;
    float mA = -1e30f, mB = -1e30f, lsA = 0.f, lsB = 0.f;

    load_kv(0, 0);
    for (int t = 0; t < SS / 64; t++) {
        if (t < SS / 64 - 1) load_kv((t + 1) & 1, (t + 1) * 64);
        if (t < SS / 64 - 1) { CP_WAIT1(); } else { CP_WAIT0(); }
        __syncthreads();
        int bi = t & 1;

#pragma unroll
        for (int cchunk = 0; cchunk < 2; cchunk++) {
            // --- S = Q K^T for 32 keys
            float s[4][4];
#pragma unroll
            for (int j = 0; j < 4; j++)
#pragma unroll
                for (int i = 0; i < 4; i++) s[j][i] = 0.f;
#pragma unroll
            for (int ks = 0; ks < 4; ks++) {
#pragma unroll
                for (int jp = 0; jp < 2; jp++) {
                    uint32_t b0, b1, b2, b3;
                    int rr = (2 * (2 * cchunk + jp) + (m >> 1)) * 8 + l7;
                    int c8 = ks * 2 + (m & 1);
                    ldm4(sK[bi] + swb(rr, c8), b0, b1, b2, b3);
                    mma_f16(s[2 * jp],     qfr[ks][0], qfr[ks][1], qfr[ks][2], qfr[ks][3], b0, b1);
                    mma_f16(s[2 * jp + 1], qfr[ks][0], qfr[ks][1], qfr[ks][2], qfr[ks][3], b2, b3);
                }
            }

            // --- online softmax over this 32-key chunk
            float tA = mA, tB = mB;
#pragma unroll
            for (int j = 0; j < 4; j++) {
                tA = fmaxf(tA, fmaxf(s[j][0], s[j][1]));
                tB = fmaxf(tB, fmaxf(s[j][2], s[j][3]));
            }
            tA = fmaxf(tA, __shfl_xor_sync(0xffffffffu, tA, 1));
            tA = fmaxf(tA, __shfl_xor_sync(0xffffffffu, tA, 2));
            tB = fmaxf(tB, __shfl_xor_sync(0xffffffffu, tB, 1));
            tB = fmaxf(tB, __shfl_xor_sync(0xffffffffu, tB, 2));
            float cA = __expf(mA - tA), cB = __expf(mB - tB);
            mA = tA; mB = tB;
            float sA = 0.f, sB = 0.f;
#pragma unroll
            for (int j = 0; j < 4; j++) {
                s[j][0] = __expf(s[j][0] - tA);
                s[j][1] = __expf(s[j][1] - tA);
                s[j][2] = __expf(s[j][2] - tB);
                s[j][3] = __expf(s[j][3] - tB);
                sA += s[j][0] + s[j][1];
                sB += s[j][2] + s[j][3];
            }
            uint32_t pa[2][4];
#pragma unroll
            for (int kk = 0; kk < 2; kk++) {
                pa[kk][0] = h2u(__floats2half2_rn(s[2 * kk][0], s[2 * kk][1]));
                pa[kk][1] = h2u(__floats2half2_rn(s[2 * kk][2], s[2 * kk][3]));
                pa[kk][2] = h2u(__floats2half2_rn(s[2 * kk + 1][0], s[2 * kk + 1][1]));
                pa[kk][3] = h2u(__floats2half2_rn(s[2 * kk + 1][2], s[2 * kk + 1][3]));
            }
            sA += __shfl_xor_sync(0xffffffffu, sA, 1);
            sA += __shfl_xor_sync(0xffffffffu, sA, 2);
            sB += __shfl_xor_sync(0xffffffffu, sB, 1);
            sB += __shfl_xor_sync(0xffffffffu, sB, 2);
            lsA = lsA * cA + sA;
            lsB = lsB * cB + sB;
#pragma unroll
            for (int j = 0; j < 8; j++) {
                o[j][0] *= cA; o[j][1] *= cA; o[j][2] *= cB; o[j][3] *= cB;
            }

            // --- O += P V for this 32-key chunk
#pragma unroll
            for (int kk = 0; kk < 2; kk++) {
#pragma unroll
                for (int jp = 0; jp < 4; jp++) {
                    uint32_t b0, b1, b2, b3;
                    int rr = (2 * jp + (m >> 1)) * 8 + l7;
                    int c8 = (2 * cchunk + kk) * 2 + (m & 1);
                    ldm4(sV[bi] + swb(rr, c8), b0, b1, b2, b3);
                    mma_f16(o[2 * jp],     pa[kk][0], pa[kk][1], pa[kk][2], pa[kk][3], b0, b1);
                    mma_f16(o[2 * jp + 1], pa[kk][0], pa[kk][1], pa[kk][2], pa[kk][3], b2, b3);
                }
            }
        }
        __syncthreads();
    }

    const float iA = 1.f / lsA, iB = 1.f / lsB;
#pragma unroll
    for (int j = 0; j < 8; j++) {
        int c = 8 * j + 2 * tig;
        *(half2*)(g_Ah + qbase + (size_t)rA * DIM + c) =
            __floats2half2_rn(o[j][0] * iA, o[j][1] * iA);
        *(half2*)(g_Ah + qbase + (size_t)(rA + 8) * DIM + c) =
            __floats2half2_rn(o[j][2] * iB, o[j][3] * iB);
    }
}

// ---------------------------------------------------------------------------
// Launch. Inputs: x, Qexpl, Kexpl, fl, fu, age, gender,
//                 Wq, bq, Wk, bk, Wv, bv, Wo, bo
// ---------------------------------------------------------------------------
extern "C" void kernel_launch(void* const* d_in, const int* in_sizes, int n_in,
                              void* d_out, int out_size) {
    const float* x     = (const float*)d_in[0];
    const float* Qexpl = (const float*)d_in[1];
    const float* Kexpl = (const float*)d_in[2];
    const float* Wq = (const float*)d_in[7];
    const float* bq = (const float*)d_in[8];
    const float* Wk = (const float*)d_in[9];
    const float* bk = (const float*)d_in[10];
    const float* Wv = (const float*)d_in[11];
    const float* bv = (const float*)d_in[12];
    const float* Wo = (const float*)d_in[13];
    const float* bo = (const float*)d_in[14];
    float* out = (float*)d_out;

    half *pxh, *pqeh, *pkeh, *pWh;
    cudaGetSymbolAddress((void**)&pxh, g_xh);
    cudaGetSymbolAddress((void**)&pqeh, g_qeh);
    cudaGetSymbolAddress((void**)&pkeh, g_keh);
    cudaGetSymbolAddress((void**)&pWh, g_Wh);

    static int smem_set = 0;
    if (!smem_set) {
        cudaFuncSetAttribute(gemm_qkv, cudaFuncAttributeMaxDynamicSharedMemorySize, GEMM_SMEM);
        cudaFuncSetAttribute(gemm_o, cudaFuncAttributeMaxDynamicSharedMemorySize, GEMM_SMEM);
        smem_set = 1;
    }

    CvtArgs ca;
    ca.s[0] = x;     ca.d[0] = pxh;                 ca.n4[0] = MROWS * DIM / 4;
    ca.s[1] = Qexpl; ca.d[1] = pqeh;                ca.n4[1] = MROWS * DIM / 4;
    ca.s[2] = Kexpl; ca.d[2] = pkeh;                ca.n4[2] = MROWS * DIM / 4;
    ca.s[3] = Wq;    ca.d[3] = pWh;                 ca.n4[3] = DIM * DIM / 4;
    ca.s[4] = Wk;    ca.d[4] = pWh + DIM * DIM;     ca.n4[4] = DIM * DIM / 4;
    ca.s[5] = Wv;    ca.d[5] = pWh + 2 * DIM * DIM; ca.n4[5] = DIM * DIM / 4;
    ca.s[6] = Wo;    ca.d[6] = pWh + 3 * DIM * DIM; ca.n4[6] = DIM * DIM / 4;
    cvt_all<<<dim3(256, 7), 256>>>(ca);

    dim3 qkvgrid(DIM / 128, MROWS / 128, 3);
    gemm_qkv<<<qkvgrid, 256, GEMM_SMEM>>>(bq, bk, bv);

    dim3 agrid(SS / 128, NHEADS, BB);
    attn_f16<<<agrid, 256>>>(nullptr);

    dim3 ogrid(DIM / 128, MROWS / 128);
    gemm_o<<<ogrid, 256, GEMM_SMEM>>>(bo, out);
}

// round 8
// speedup vs baseline: 11.7449x; 1.0212x over previous
#include <cuda_runtime.h>
#include <cuda_fp16.h>
#include <stdint.h>

#define DIM 512
#define NHEADS 8
#define HD 64
#define BB 2
#define SS 2048
#define MROWS (BB*SS)   // 4096

// Scratch (static device allocation — allowed)
__device__ half g_xh[MROWS * DIM];
__device__ half g_qeh[MROWS * DIM];
__device__ half g_keh[MROWS * DIM];
__device__ half g_Wh[4][DIM * DIM];      // Wq, Wk, Wv, Wo as half
__device__ half g_Qh[MROWS * DIM];       // Q proj (pre-scaled by 0.125*log2e)
__device__ half g_Kh[MROWS * DIM];
__device__ half g_Vth[DIM * MROWS];      // V proj TRANSPOSED [dim][token]
__device__ half g_Ah[MROWS * DIM];       // attention output (half)

// ---------------------------------------------------------------------------
// helpers
// ---------------------------------------------------------------------------
__device__ __forceinline__ void mma_f16(float c[4],
                                        uint32_t a0, uint32_t a1, uint32_t a2, uint32_t a3,
                                        uint32_t b0, uint32_t b1) {
    asm volatile(
        "mma.sync.aligned.m16n8k16.row.col.f32.f16.f16.f32 "
        "{%0,%1,%2,%3}, {%4,%5,%6,%7}, {%8,%9}, {%0,%1,%2,%3};"
        : "+f"(c[0]), "+f"(c[1]), "+f"(c[2]), "+f"(c[3])
        : "r"(a0), "r"(a1), "r"(a2), "r"(a3), "r"(b0), "r"(b1));
}

__device__ __forceinline__ uint32_t h2u(half2 h) { return *(uint32_t*)&h; }

__device__ __forceinline__ uint2 f4h4(float4 v) {
    half2 lo = __floats2half2_rn(v.x, v.y);
    half2 hi = __floats2half2_rn(v.z, v.w);
    return make_uint2(h2u(lo), h2u(hi));
}

__device__ __forceinline__ void ldm4(uint32_t addr, uint32_t& r0, uint32_t& r1,
                                     uint32_t& r2, uint32_t& r3) {
    asm volatile("ldmatrix.sync.aligned.m8n8.x4.shared.b16 {%0,%1,%2,%3}, [%4];"
                 : "=r"(r0), "=r"(r1), "=r"(r2), "=r"(r3) : "r"(addr));
}

#define CP16(dst, src) \
    asm volatile("cp.async.cg.shared.global [%0], [%1], 16;" :: "r"(dst), "l"(src))
#define CP_COMMIT() asm volatile("cp.async.commit_group;")
#define CP_WAIT1()  asm volatile("cp.async.wait_group 1;")
#define CP_WAIT0()  asm volatile("cp.async.wait_group 0;")

// rows of 128B = 8 chunks of 16B, XOR-swizzled by row&7.
__device__ __forceinline__ uint32_t swb(int r, int c8) {
    return (uint32_t)(r * 128 + ((c8 ^ (r & 7)) << 4));
}

// ---------------------------------------------------------------------------
// fp32 -> fp16 conversion, 7 planes
// ---------------------------------------------------------------------------
struct CvtArgs {
    const float* s[7];
    half* d[7];
    int n4[7];
};

__global__ __launch_bounds__(256) void cvt_all(CvtArgs a) {
    int z = blockIdx.y;
    int n4 = a.n4[z];
    const float4* s = (const float4*)a.s[z];
    half* d = a.d[z];
    for (int i = blockIdx.x * blockDim.x + threadIdx.x; i < n4;
         i += gridDim.x * blockDim.x) {
        float4 v = s[i];
        *(uint2*)(d + (size_t)i * 4) = f4h4(v);
    }
}

// ---------------------------------------------------------------------------
// C[M,N] = A[M,K] @ W[N,K]^T + bias  (NT, half in, fp16 mma).
// 128 x NTILE tile, 256 thr (8 warps: 4 row-groups x 2 col-groups),
// 64-deep k chunks, double-buffered cp.async, ldmatrix frags.
// ---------------------------------------------------------------------------
template<int NTILE>
__device__ __forceinline__ void gemm_body(const half* __restrict__ A,
                                          const half* __restrict__ W,
                                          const float* __restrict__ bias,
                                          float scale,
                                          float* Cf, half* Ch, half* Ct,
                                          int row0, int col0, half* smem) {
    const int tid = threadIdx.x;
    const int w = tid >> 5, lane = tid & 31;
    const int tig = lane & 3, lg = lane >> 2;
    const int m = lane >> 3, l7 = lane & 7;
    const int wr = w & 3;    // row group (32 rows)
    const int wc = w >> 2;   // col group (NTILE/2 cols)
    constexpr int JP = NTILE / 32;          // b-frag loads per k-step
    constexpr uint32_t WB = NTILE * 128;    // W buffer bytes

    uint32_t sbase = (uint32_t)__cvta_generic_to_shared(smem);
    const uint32_t sA[2] = { sbase, sbase + 16384 + WB };
    const uint32_t sW[2] = { sbase + 16384, sbase + 32768 + WB };

    float acc[2][2 * JP][4];
#pragma unroll
    for (int g = 0; g < 2; g++)
#pragma unroll
        for (int j = 0; j < 2 * JP; j++)
#pragma unroll
            for (int i = 0; i < 4; i++) acc[g][j][i] = 0.f;

    auto load_stage = [&](int bi, int kc) {
#pragma unroll
        for (int i = 0; i < 4; i++) {           // A: 128 rows x 8 chunks
            int idx = tid + i * 256;
            int r = idx >> 3, c8 = idx & 7;
            CP16(sA[bi] + swb(r, c8), A + (size_t)(row0 + r) * DIM + kc + c8 * 8);
        }
#pragma unroll
        for (int i = 0; i < NTILE / 32; i++) {  // W: NTILE rows x 8 chunks
            int idx = tid + i * 256;
            int r = idx >> 3, c8 = idx & 7;
            CP16(sW[bi] + swb(r, c8), W + (size_t)(col0 + r) * DIM + kc + c8 * 8);
        }
        CP_COMMIT();
    };

    load_stage(0, 0);
    for (int c = 0; c < 8; c++) {
        if (c < 7) load_stage((c + 1) & 1, (c + 1) * 64);
        if (c < 7) { CP_WAIT1(); } else { CP_WAIT0(); }
        __syncthreads();
        int bi = c & 1;
#pragma unroll
        for (int ks = 0; ks < 4; ks++) {
            uint32_t af[2][4];
#pragma unroll
            for (int g = 0; g < 2; g++) {
                int rr = wr * 32 + g * 16 + ((m & 1) << 3) + l7;
                int c8 = ks * 2 + (m >> 1);
                ldm4(sA[bi] + swb(rr, c8), af[g][0], af[g][1], af[g][2], af[g][3]);
            }
#pragma unroll
            for (int jp = 0; jp < JP; jp++) {
                uint32_t b0, b1, b2, b3;
                int rr = wc * (NTILE / 2) + (2 * jp + (m >> 1)) * 8 + l7;
                int c8 = ks * 2 + (m & 1);
                ldm4(sW[bi] + swb(rr, c8), b0, b1, b2, b3);
#pragma unroll
                for (int g = 0; g < 2; g++) {
                    mma_f16(acc[g][2 * jp],     af[g][0], af[g][1], af[g][2], af[g][3], b0, b1);
                    mma_f16(acc[g][2 * jp + 1], af[g][0], af[g][1], af[g][2], af[g][3], b2, b3);
                }
            }
        }
        __syncthreads();
    }

#pragma unroll
    for (int g = 0; g < 2; g++) {
        const int gr = row0 + wr * 32 + g * 16 + lg;
#pragma unroll
        for (int j = 0; j < 2 * JP; j++) {
            int c = col0 + wc * (NTILE / 2) + 8 * j + 2 * tig;
            float b0v = bias[c], b1v = bias[c + 1];
            float v0 = (acc[g][j][0] + b0v) * scale;
            float v1 = (acc[g][j][1] + b1v) * scale;
            float v2 = (acc[g][j][2] + b0v) * scale;
            float v3 = (acc[g][j][3] + b1v) * scale;
            if (Ch) {
                *(half2*)(Ch + (size_t)gr * DIM + c) = __floats2half2_rn(v0, v1);
                *(half2*)(Ch + (size_t)(gr + 8) * DIM + c) = __floats2half2_rn(v2, v3);
            } else if (Ct) {
                Ct[(size_t)c * MROWS + gr] = __float2half(v0);
                Ct[(size_t)(c + 1) * MROWS + gr] = __float2half(v1);
                Ct[(size_t)c * MROWS + gr + 8] = __float2half(v2);
                Ct[(size_t)(c + 1) * MROWS + gr + 8] = __float2half(v3);
            } else {
                *(float2*)(Cf + (size_t)gr * DIM + c) = make_float2(v0, v1);
                *(float2*)(Cf + (size_t)(gr + 8) * DIM + c) = make_float2(v2, v3);
            }
        }
    }
}

#define QKV_SMEM 65536
#define O_SMEM   49152
#define QSCALE   0.18033688011112042f   // 0.125 * log2(e)

__global__ __launch_bounds__(256, 2) void gemm_qkv(const float* __restrict__ bq,
                                                   const float* __restrict__ bk,
                                                   const float* __restrict__ bv) {
    extern __shared__ __align__(16) half smem[];
    int z = blockIdx.z;
    const half* A = (z == 0) ? g_qeh : (z == 1) ? g_keh : g_xh;
    const half* W = g_Wh[z];
    const float* bias = (z == 0) ? bq : (z == 1) ? bk : bv;
    float scale = (z == 0) ? QSCALE : 1.0f;
    half* Ch = (z == 0) ? g_Qh : (z == 1) ? g_Kh : nullptr;
    half* Ct = (z == 2) ? g_Vth : nullptr;
    gemm_body<128>(A, W, bias, scale, nullptr, Ch, Ct,
                   blockIdx.y * 128, blockIdx.x * 128, smem);
}

__global__ __launch_bounds__(256, 2) void gemm_o(const float* __restrict__ bo,
                                                 float* __restrict__ out) {
    extern __shared__ __align__(16) half smem[];
    gemm_body<64>(g_Ah, g_Wh[3], bo, 1.0f, out, nullptr, nullptr,
                  blockIdx.y * 128, blockIdx.x * 64, smem);
}

// ---------------------------------------------------------------------------
// Flash attention: 128 queries/block, 256 thr (8 warps x 16 rows), fp16 mma.
// Q pre-scaled by 0.125*log2e -> softmax uses exp2f. 64-key tiles
// (double-buffered cp.async) processed as TWO 32-key softmax chunks.
// grid = (S/128, H, B).
// ---------------------------------------------------------------------------
__global__ __launch_bounds__(256, 2) void attn_f16(float* __restrict__ dummy) {
    __shared__ __align__(16) half smK[2][4096];
    __shared__ __align__(16) half smV[2][4096];

    const int tid = threadIdx.x;
    const int w = tid >> 5, lane = tid & 31;
    const int tig = lane & 3, lg = lane >> 2;
    const int m = lane >> 3, l7 = lane & 7;
    const int q0 = blockIdx.x * 128;
    const int h = blockIdx.y;
    const int b = blockIdx.z;
    const size_t qbase = (size_t)(b * SS + q0) * DIM + h * HD;
    const int rA = 16 * w + lg;

    uint32_t sK[2], sV[2];
    sK[0] = (uint32_t)__cvta_generic_to_shared(smK[0]);
    sK[1] = (uint32_t)__cvta_generic_to_shared(smK[1]);
    sV[0] = (uint32_t)__cvta_generic_to_shared(smV[0]);
    sV[1] = (uint32_t)__cvta_generic_to_shared(smV[1]);

    // ---- stage Q (128 rows x 64) through smK[0..1] (16KB contiguous)
#pragma unroll
    for (int i = 0; i < 4; i++) {
        int idx = tid + i * 256;
        int r = idx >> 3, c8 = idx & 7;
        CP16(sK[0] + swb(r, c8), g_Qh + qbase + (size_t)r * DIM + c8 * 8);
    }
    CP_COMMIT(); CP_WAIT0();
    __syncthreads();
    uint32_t qfr[4][4];
#pragma unroll
    for (int ks = 0; ks < 4; ks++) {
        int rr = 16 * w + ((m & 1) << 3) + l7;
        int c8 = ks * 2 + (m >> 1);
        ldm4(sK[0] + swb(rr, c8), qfr[ks][0], qfr[ks][1], qfr[ks][2], qfr[ks][3]);
    }
    __syncthreads();

    auto load_kv = [&](int bi, int kt) {
        const size_t kbase = (size_t)(b * SS + kt) * DIM + h * HD;
#pragma unroll
        for (int i = 0; i < 2; i++) {
            int idx = tid + i * 256;
            int r = idx >> 3, c8 = idx & 7;
            CP16(sK[bi] + swb(r, c8), g_Kh + kbase + (size_t)r * DIM + c8 * 8);
            CP16(sV[bi] + swb(r, c8),
                 g_Vth + (size_t)(h * HD + r) * MROWS + b * SS + kt + c8 * 8);
        }
        CP_COMMIT();
    };

    float o[8][4];
#pragma unroll
    for (int j = 0; j < 8; j++)
#pragma unroll
        for (int i = 0; i < 4; i++) o[j][i] = 0.f;
    float mA = -1e30f, mB = -1e30f, lsA = 0.f, lsB = 0.f;

    load_kv(0, 0);
    for (int t = 0; t < SS / 64; t++) {
        if (t < SS / 64 - 1) load_kv((t + 1) & 1, (t + 1) * 64);
        if (t < SS / 64 - 1) { CP_WAIT1(); } else { CP_WAIT0(); }
        __syncthreads();
        int bi = t & 1;

#pragma unroll
        for (int cchunk = 0; cchunk < 2; cchunk++) {
            // --- S = Q K^T for 32 keys (in log2e-scaled domain)
            float s[4][4];
#pragma unroll
            for (int j = 0; j < 4; j++)
#pragma unroll
                for (int i = 0; i < 4; i++) s[j][i] = 0.f;
#pragma unroll
            for (int ks = 0; ks < 4; ks++) {
#pragma unroll
                for (int jp = 0; jp < 2; jp++) {
                    uint32_t b0, b1, b2, b3;
                    int rr = (2 * (2 * cchunk + jp) + (m >> 1)) * 8 + l7;
                    int c8 = ks * 2 + (m & 1);
                    ldm4(sK[bi] + swb(rr, c8), b0, b1, b2, b3);
                    mma_f16(s[2 * jp],     qfr[ks][0], qfr[ks][1], qfr[ks][2], qfr[ks][3], b0, b1);
                    mma_f16(s[2 * jp + 1], qfr[ks][0], qfr[ks][1], qfr[ks][2], qfr[ks][3], b2, b3);
                }
            }

            // --- online softmax over this 32-key chunk (base-2 exps)
            float tA = mA, tB = mB;
#pragma unroll
            for (int j = 0; j < 4; j++) {
                tA = fmaxf(tA, fmaxf(s[j][0], s[j][1]));
                tB = fmaxf(tB, fmaxf(s[j][2], s[j][3]));
            }
            tA = fmaxf(tA, __shfl_xor_sync(0xffffffffu, tA, 1));
            tA = fmaxf(tA, __shfl_xor_sync(0xffffffffu, tA, 2));
            tB = fmaxf(tB, __shfl_xor_sync(0xffffffffu, tB, 1));
            tB = fmaxf(tB, __shfl_xor_sync(0xffffffffu, tB, 2));
            float cA = exp2f(mA - tA), cB = exp2f(mB - tB);
            mA = tA; mB = tB;
            float sA = 0.f, sB = 0.f;
#pragma unroll
            for (int j = 0; j < 4; j++) {
                s[j][0] = exp2f(s[j][0] - tA);
                s[j][1] = exp2f(s[j][1] - tA);
                s[j][2] = exp2f(s[j][2] - tB);
                s[j][3] = exp2f(s[j][3] - tB);
                sA += s[j][0] + s[j][1];
                sB += s[j][2] + s[j][3];
            }
            uint32_t pa[2][4];
#pragma unroll
            for (int kk = 0; kk < 2; kk++) {
                pa[kk][0] = h2u(__floats2half2_rn(s[2 * kk][0], s[2 * kk][1]));
                pa[kk][1] = h2u(__floats2half2_rn(s[2 * kk][2], s[2 * kk][3]));
                pa[kk][2] = h2u(__floats2half2_rn(s[2 * kk + 1][0], s[2 * kk + 1][1]));
                pa[kk][3] = h2u(__floats2half2_rn(s[2 * kk + 1][2], s[2 * kk + 1][3]));
            }
            sA += __shfl_xor_sync(0xffffffffu, sA, 1);
            sA += __shfl_xor_sync(0xffffffffu, sA, 2);
            sB += __shfl_xor_sync(0xffffffffu, sB, 1);
            sB += __shfl_xor_sync(0xffffffffu, sB, 2);
            lsA = lsA * cA + sA;
            lsB = lsB * cB + sB;
#pragma unroll
            for (int j = 0; j < 8; j++) {
                o[j][0] *= cA; o[j][1] *= cA; o[j][2] *= cB; o[j][3] *= cB;
            }

            // --- O += P V for this 32-key chunk
#pragma unroll
            for (int kk = 0; kk < 2; kk++) {
#pragma unroll
                for (int jp = 0; jp < 4; jp++) {
                    uint32_t b0, b1, b2, b3;
                    int rr = (2 * jp + (m >> 1)) * 8 + l7;
                    int c8 = (2 * cchunk + kk) * 2 + (m & 1);
                    ldm4(sV[bi] + swb(rr, c8), b0, b1, b2, b3);
                    mma_f16(o[2 * jp],     pa[kk][0], pa[kk][1], pa[kk][2], pa[kk][3], b0, b1);
                    mma_f16(o[2 * jp + 1], pa[kk][0], pa[kk][1], pa[kk][2], pa[kk][3], b2, b3);
                }
            }
        }
        __syncthreads();
    }

    const float iA = 1.f / lsA, iB = 1.f / lsB;
#pragma unroll
    for (int j = 0; j < 8; j++) {
        int c = 8 * j + 2 * tig;
        *(half2*)(g_Ah + qbase + (size_t)rA * DIM + c) =
            __floats2half2_rn(o[j][0] * iA, o[j][1] * iA);
        *(half2*)(g_Ah + qbase + (size_t)(rA + 8) * DIM + c) =
            __floats2half2_rn(o[j][2] * iB, o[j][3] * iB);
    }
}

// ---------------------------------------------------------------------------
// Launch. Inputs: x, Qexpl, Kexpl, fl, fu, age, gender,
//                 Wq, bq, Wk, bk, Wv, bv, Wo, bo
// ---------------------------------------------------------------------------
extern "C" void kernel_launch(void* const* d_in, const int* in_sizes, int n_in,
                              void* d_out, int out_size) {
    const float* x     = (const float*)d_in[0];
    const float* Qexpl = (const float*)d_in[1];
    const float* Kexpl = (const float*)d_in[2];
    const float* Wq = (const float*)d_in[7];
    const float* bq = (const float*)d_in[8];
    const float* Wk = (const float*)d_in[9];
    const float* bk = (const float*)d_in[10];
    const float* Wv = (const float*)d_in[11];
    const float* bv = (const float*)d_in[12];
    const float* Wo = (const float*)d_in[13];
    const float* bo = (const float*)d_in[14];
    float* out = (float*)d_out;

    half *pxh, *pqeh, *pkeh, *pWh;
    cudaGetSymbolAddress((void**)&pxh, g_xh);
    cudaGetSymbolAddress((void**)&pqeh, g_qeh);
    cudaGetSymbolAddress((void**)&pkeh, g_keh);
    cudaGetSymbolAddress((void**)&pWh, g_Wh);

    static int smem_set = 0;
    if (!smem_set) {
        cudaFuncSetAttribute(gemm_qkv, cudaFuncAttributeMaxDynamicSharedMemorySize, QKV_SMEM);
        cudaFuncSetAttribute(gemm_o, cudaFuncAttributeMaxDynamicSharedMemorySize, O_SMEM);
        smem_set = 1;
    }

    CvtArgs ca;
    ca.s[0] = x;     ca.d[0] = pxh;                 ca.n4[0] = MROWS * DIM / 4;
    ca.s[1] = Qexpl; ca.d[1] = pqeh;                ca.n4[1] = MROWS * DIM / 4;
    ca.s[2] = Kexpl; ca.d[2] = pkeh;                ca.n4[2] = MROWS * DIM / 4;
    ca.s[3] = Wq;    ca.d[3] = pWh;                 ca.n4[3] = DIM * DIM / 4;
    ca.s[4] = Wk;    ca.d[4] = pWh + DIM * DIM;     ca.n4[4] = DIM * DIM / 4;
    ca.s[5] = Wv;    ca.d[5] = pWh + 2 * DIM * DIM; ca.n4[5] = DIM * DIM / 4;
    ca.s[6] = Wo;    ca.d[6] = pWh + 3 * DIM * DIM; ca.n4[6] = DIM * DIM / 4;
    cvt_all<<<dim3(256, 7), 256>>>(ca);

    dim3 qkvgrid(DIM / 128, MROWS / 128, 3);
    gemm_qkv<<<qkvgrid, 256, QKV_SMEM>>>(bq, bk, bv);

    dim3 agrid(SS / 128, NHEADS, BB);
    attn_f16<<<agrid, 256>>>(nullptr);

    dim3 ogrid(DIM / 64, MROWS / 128);
    gemm_o<<<ogrid, 256, O_SMEM>>>(bo, out);
}